// round 11
// baseline (speedup 1.0000x reference)
#include <cuda_runtime.h>
#include <cuda_bf16.h>
#include <cstdint>

#define B_ 4
#define L_ 2048
#define C_ 1024
#define H_ 16
#define D_ 64
#define MTOK (B_ * L_)   // 8192 token rows

// ---------------------------------------------------------------------------
// Scratch (allocation-free rule: __device__ globals)
// ---------------------------------------------------------------------------
__device__ __nv_bfloat16 g_Ahi[(size_t)MTOK * C_];     // activation hi  [M,K]
__device__ __nv_bfloat16 g_Alo[(size_t)MTOK * C_];     // activation lo  [M,K]
__device__ __nv_bfloat16 g_Bhi[(size_t)3 * C_ * C_];   // weight^T hi    [N,K]
__device__ __nv_bfloat16 g_Blo[(size_t)3 * C_ * C_];   // weight^T lo    [N,K]
__device__ __nv_bfloat16 g_Shi[(size_t)MTOK * 3 * C_]; // QKV hi [8192,3072]
__device__ __nv_bfloat16 g_Slo[(size_t)MTOK * 3 * C_]; // QKV lo

// ---------------------------------------------------------------------------
// helpers
// ---------------------------------------------------------------------------
__device__ __forceinline__ uint32_t smem_u32(const void* p) {
    return (uint32_t)__cvta_generic_to_shared(p);
}
__device__ __forceinline__ void cp16(void* s, const void* g) {
    uint32_t sa = smem_u32(s);
    asm volatile("cp.async.cg.shared.global [%0], [%1], 16;" :: "r"(sa), "l"(g) : "memory");
}
__device__ __forceinline__ void ldx4(uint32_t* r, uint32_t addr) {
    asm volatile("ldmatrix.sync.aligned.m8n8.x4.shared.b16 {%0,%1,%2,%3}, [%4];"
                 : "=r"(r[0]), "=r"(r[1]), "=r"(r[2]), "=r"(r[3]) : "r"(addr));
}
__device__ __forceinline__ void ldx4t(uint32_t* r, uint32_t addr) {
    asm volatile("ldmatrix.sync.aligned.m8n8.x4.trans.shared.b16 {%0,%1,%2,%3}, [%4];"
                 : "=r"(r[0]), "=r"(r[1]), "=r"(r[2]), "=r"(r[3]) : "r"(addr));
}
__device__ __forceinline__ void mma_bf16(float* d, const uint32_t* a, const uint32_t* b) {
    asm volatile(
        "mma.sync.aligned.m16n8k16.row.col.f32.bf16.bf16.f32 "
        "{%0,%1,%2,%3}, {%4,%5,%6,%7}, {%8,%9}, {%0,%1,%2,%3};"
        : "+f"(d[0]), "+f"(d[1]), "+f"(d[2]), "+f"(d[3])
        : "r"(a[0]), "r"(a[1]), "r"(a[2]), "r"(a[3]), "r"(b[0]), "r"(b[1]));
}
// pack two floats into bf16x2 hi + bf16x2 lo (residual)
__device__ __forceinline__ void pack_hilo(float a, float b, uint32_t& h, uint32_t& l) {
    __nv_bfloat162 hv = __floats2bfloat162_rn(a, b);
    float2 hf = __bfloat1622float2(hv);
    __nv_bfloat162 lv = __floats2bfloat162_rn(a - hf.x, b - hf.y);
    h = *(uint32_t*)&hv;
    l = *(uint32_t*)&lv;
}

// ---------------------------------------------------------------------------
// fp32 -> bf16 hi/lo split (same layout)
// ---------------------------------------------------------------------------
__global__ __launch_bounds__(256) void cvt_hilo(
    const float* __restrict__ in, __nv_bfloat16* __restrict__ hi,
    __nv_bfloat16* __restrict__ lo, int n)
{
    int i = (blockIdx.x * 256 + threadIdx.x) * 4;
    if (i >= n) return;
    float4 v = *(const float4*)(in + i);
    float f[4] = {v.x, v.y, v.z, v.w};
    __align__(8) __nv_bfloat16 hb[4];
    __align__(8) __nv_bfloat16 lb[4];
#pragma unroll
    for (int j = 0; j < 4; j++) {
        hb[j] = __float2bfloat16(f[j]);
        lb[j] = __float2bfloat16(f[j] - __bfloat162float(hb[j]));
    }
    *(uint2*)(hi + i) = *(uint2*)hb;
    *(uint2*)(lo + i) = *(uint2*)lb;
}

// ---------------------------------------------------------------------------
// W [K,N] fp32 row-major -> W^T hi/lo bf16 [N,K]
// ---------------------------------------------------------------------------
__global__ __launch_bounds__(256) void cvt_w_t(
    const float* __restrict__ W, __nv_bfloat16* __restrict__ Thi,
    __nv_bfloat16* __restrict__ Tlo, int K, int N)
{
    __shared__ float tile[32][33];
    const int n0 = blockIdx.x * 32, k0 = blockIdx.y * 32;
    const int tx = threadIdx.x & 31, ty = threadIdx.x >> 5;   // 32 x 8
#pragma unroll
    for (int r = 0; r < 4; r++)
        tile[ty + 8 * r][tx] = W[(size_t)(k0 + ty + 8 * r) * N + n0 + tx];
    __syncthreads();
#pragma unroll
    for (int r = 0; r < 4; r++) {
        int n = n0 + ty + 8 * r;
        float v = tile[tx][ty + 8 * r];
        __nv_bfloat16 h = __float2bfloat16(v);
        __nv_bfloat16 l = __float2bfloat16(v - __bfloat162float(h));
        Thi[(size_t)n * K + k0 + tx] = h;
        Tlo[(size_t)n * K + k0 + tx] = l;
    }
}

// ---------------------------------------------------------------------------
// mma.sync bf16x3 GEMM: C[M,N] = A[M,K] @ B^T  (A [M,K], B [N,K], hi/lo bf16)
// CTA: 128x128 tile, BK=32, 256 threads (8 warps, 2Mx4N, warp tile 64x32),
// cp.async double-buffered. Split products issued product-outermost so
// consecutive mma.sync never share an accumulator (RAW chain breaker).
// MODE 0: fp32 out; MODE 1: hi/lo bf16 out.
// ---------------------------------------------------------------------------
#define BK_G   32
#define LDT    40                       // 32 + 8 pad (bf16 elems) -> 80B rows
#define MAT_B  (128 * LDT * 2)          // 10240 B per matrix (128 rows)
#define BUF_B  (4 * MAT_B)              // Ahi Alo Bhi Blo = 40960 B
#define SMEM_GEMM (2 * BUF_B)           // 81920 B

template<int MODE>
__global__ __launch_bounds__(256, 1)
void gemm_mma_bf16x3(const __nv_bfloat16* __restrict__ Ahi,
                     const __nv_bfloat16* __restrict__ Alo,
                     const __nv_bfloat16* __restrict__ Bhi,
                     const __nv_bfloat16* __restrict__ Blo,
                     float* __restrict__ Cf,
                     __nv_bfloat16* __restrict__ Chi,
                     __nv_bfloat16* __restrict__ Clo,
                     int N, int K)
{
    extern __shared__ __align__(128) char smem[];
    const int t    = threadIdx.x;
    const int lane = t & 31;
    const int wid  = t >> 5;
    const int bn   = blockIdx.x * 128;
    const int bm   = blockIdx.y * 128;
    const int wm   = (wid & 1) * 64;
    const int wn   = (wid >> 1) * 32;

    float acc[4][4][4];
#pragma unroll
    for (int i = 0; i < 4; i++)
#pragma unroll
        for (int j = 0; j < 4; j++)
#pragma unroll
            for (int r = 0; r < 4; r++) acc[i][j][r] = 0.f;

    const int nk = K / BK_G;

    auto load_tile = [&](int c, int buf) {
        char* bp = smem + buf * BUF_B;
        const int kc = c * BK_G;
#pragma unroll
        for (int i = 0; i < 2; i++) {
            int idx = t + 256 * i;
            int row = idx >> 2;
            int c16 = idx & 3;
            uint32_t so = (uint32_t)(row * LDT + c16 * 8) * 2;
            size_t ga = (size_t)(bm + row) * K + kc + c16 * 8;
            size_t gb = (size_t)(bn + row) * K + kc + c16 * 8;
            cp16(bp + so,             Ahi + ga);
            cp16(bp + MAT_B + so,     Alo + ga);
            cp16(bp + 2 * MAT_B + so, Bhi + gb);
            cp16(bp + 3 * MAT_B + so, Blo + gb);
        }
    };

    load_tile(0, 0);
    asm volatile("cp.async.commit_group;" ::: "memory");

    for (int c = 0; c < nk; c++) {
        if (c + 1 < nk) {
            load_tile(c + 1, (c + 1) & 1);
            asm volatile("cp.async.commit_group;" ::: "memory");
            asm volatile("cp.async.wait_group 1;" ::: "memory");
        } else {
            asm volatile("cp.async.wait_group 0;" ::: "memory");
        }
        __syncthreads();

        const char* bp = smem + (c & 1) * BUF_B;
        const __nv_bfloat16* sAhi = (const __nv_bfloat16*)(bp);
        const __nv_bfloat16* sAlo = (const __nv_bfloat16*)(bp + MAT_B);
        const __nv_bfloat16* sBhi = (const __nv_bfloat16*)(bp + 2 * MAT_B);
        const __nv_bfloat16* sBlo = (const __nv_bfloat16*)(bp + 3 * MAT_B);

#pragma unroll
        for (int ks = 0; ks < BK_G; ks += 16) {
            uint32_t ah[4][4], al[4][4], bh[2][4], bl[2][4];
            const int arow = lane & 15;
            const int acol = ks + (lane >> 4) * 8;
#pragma unroll
            for (int mf = 0; mf < 4; mf++) {
                uint32_t off = (uint32_t)((wm + mf * 16 + arow) * LDT + acol);
                ldx4(ah[mf], smem_u32(sAhi + off));
                ldx4(al[mf], smem_u32(sAlo + off));
            }
            const int g    = lane >> 3;
            const int brow = ((g >> 1) << 3) + (lane & 7);
            const int bcol = ks + (g & 1) * 8;
#pragma unroll
            for (int nf2 = 0; nf2 < 2; nf2++) {
                uint32_t off = (uint32_t)((wn + nf2 * 16 + brow) * LDT + bcol);
                ldx4(bh[nf2], smem_u32(sBhi + off));
                ldx4(bl[nf2], smem_u32(sBlo + off));
            }
            // product-outermost: 16 distinct accumulators between reuse
#pragma unroll
            for (int p = 0; p < 3; p++)
#pragma unroll
                for (int mf = 0; mf < 4; mf++)
#pragma unroll
                    for (int nf2 = 0; nf2 < 2; nf2++)
#pragma unroll
                        for (int j = 0; j < 2; j++) {
                            const uint32_t* av = (p == 2) ? al[mf] : ah[mf];
                            const uint32_t* bv = (p == 1) ? &bl[nf2][j * 2]
                                                          : &bh[nf2][j * 2];
                            mma_bf16(acc[mf][nf2 * 2 + j], av, bv);
                        }
        }
        __syncthreads();
    }

#pragma unroll
    for (int mf = 0; mf < 4; mf++)
#pragma unroll
        for (int nf = 0; nf < 4; nf++) {
            int row = bm + wm + mf * 16 + (lane >> 2);
            int col = bn + wn + nf * 8 + (lane & 3) * 2;
            if (MODE == 0) {
                *(float2*)&Cf[(size_t)row * N + col] =
                    make_float2(acc[mf][nf][0], acc[mf][nf][1]);
                *(float2*)&Cf[(size_t)(row + 8) * N + col] =
                    make_float2(acc[mf][nf][2], acc[mf][nf][3]);
            } else {
                uint32_t h, l;
                pack_hilo(acc[mf][nf][0], acc[mf][nf][1], h, l);
                *(uint32_t*)&Chi[(size_t)row * N + col] = h;
                *(uint32_t*)&Clo[(size_t)row * N + col] = l;
                pack_hilo(acc[mf][nf][2], acc[mf][nf][3], h, l);
                *(uint32_t*)&Chi[(size_t)(row + 8) * N + col] = h;
                *(uint32_t*)&Clo[(size_t)(row + 8) * N + col] = l;
            }
        }
}

// ---------------------------------------------------------------------------
// Tensor-core flash attention (bf16x3 hi/lo, fp32 accum).
// CTA: 256 threads (8 warps), BLOCK_M=128 q, BLOCK_N=64 k. Warp owns 16 q rows.
// K/V tiles double-buffered with cp.async. Split-product mmas interleaved.
// ---------------------------------------------------------------------------
#define LDA_A 72
#define QTILE_E (128 * LDA_A)
#define KVTILE_E (64 * LDA_A)
// Qh Ql | stage0: Kh Kl Vh Vl | stage1: Kh Kl Vh Vl
#define ATTN_SMEM ((2 * QTILE_E + 8 * KVTILE_E) * 2)   // 110592 B

__global__ __launch_bounds__(256) void attn_mma(
    const __nv_bfloat16* __restrict__ Shi, const __nv_bfloat16* __restrict__ Slo,
    __nv_bfloat16* __restrict__ Yhi, __nv_bfloat16* __restrict__ Ylo)
{
    extern __shared__ __align__(16) char smraw[];
    __nv_bfloat16* Qh = (__nv_bfloat16*)smraw;
    __nv_bfloat16* Ql = Qh + QTILE_E;
    __nv_bfloat16* KV0 = Ql + QTILE_E;   // per stage: Kh Kl Vh Vl

    const int it = blockIdx.x;          // q-tile of 128 (0..15)
    const int h  = blockIdx.y;
    const int b  = blockIdx.z;
    const int t  = threadIdx.x;
    const int lane = t & 31;
    const int wid  = t >> 5;
    const int wq   = wid * 16;          // warp's q-row offset in 128-row tile

    const int q0   = it * 128;
    const size_t tok0 = (size_t)b * L_;
    const int qcol = h * D_;
    const int kcol = C_ + h * D_;
    const int vcol = 2 * C_ + h * D_;

    auto load_kv = [&](int jb, int st) {
        __nv_bfloat16* base = KV0 + st * 4 * KVTILE_E;
        const int k0 = jb * 64;
#pragma unroll
        for (int i = 0; i < 2; i++) {
            int idx = t + 256 * i;
            int row = idx >> 3;
            int ch  = (idx & 7) * 8;
            size_t gk = (tok0 + k0 + row) * (3 * C_) + kcol + ch;
            size_t gv = (tok0 + k0 + row) * (3 * C_) + vcol + ch;
            uint32_t so = row * LDA_A + ch;
            cp16(base + so,                Shi + gk);
            cp16(base + KVTILE_E + so,     Slo + gk);
            cp16(base + 2 * KVTILE_E + so, Shi + gv);
            cp16(base + 3 * KVTILE_E + so, Slo + gv);
        }
    };

    // ---- stage Q tile (hi/lo) as group 0; K/V block 0 as group 1 ----
#pragma unroll
    for (int i = 0; i < 4; i++) {
        int idx = t + 256 * i;
        int row = idx >> 3;
        int ch  = (idx & 7) * 8;
        size_t g = (tok0 + q0 + row) * (3 * C_) + qcol + ch;
        cp16(Qh + row * LDA_A + ch, Shi + g);
        cp16(Ql + row * LDA_A + ch, Slo + g);
    }
    asm volatile("cp.async.commit_group;" ::: "memory");
    load_kv(0, 0);
    asm volatile("cp.async.commit_group;" ::: "memory");
    asm volatile("cp.async.wait_group 1;" ::: "memory");   // Q ready
    __syncthreads();

    // ---- Q fragments (A-frags, m16k16 x 4 kgroups, hi+lo) ----
    uint32_t qh[4][4], ql[4][4];
    {
        const int arow = lane & 15;
        const int acol = (lane >> 4) * 8;
#pragma unroll
        for (int kg = 0; kg < 4; kg++) {
            uint32_t off = (uint32_t)((wq + arow) * LDA_A + kg * 16 + acol);
            ldx4(qh[kg], smem_u32(Qh + off));
            ldx4(ql[kg], smem_u32(Ql + off));
        }
    }

    const int r0 = lane >> 2;
    float m[2] = {-1e30f, -1e30f};
    float lsum[2] = {0.f, 0.f};
    float O[8][4];
#pragma unroll
    for (int f = 0; f < 8; f++)
#pragma unroll
        for (int e = 0; e < 4; e++) O[f][e] = 0.f;

    const int nb = 2 * it + 2;          // k-blocks of 64 covering q0..q0+127

    for (int jb = 0; jb < nb; jb++) {
        const int k0 = jb * 64;
        if (jb + 1 < nb) {
            load_kv(jb + 1, (jb + 1) & 1);
            asm volatile("cp.async.commit_group;" ::: "memory");
            asm volatile("cp.async.wait_group 1;" ::: "memory");
        } else {
            asm volatile("cp.async.wait_group 0;" ::: "memory");
        }
        __syncthreads();

        const __nv_bfloat16* base = KV0 + (jb & 1) * 4 * KVTILE_E;
        const __nv_bfloat16* Kh = base;
        const __nv_bfloat16* Kl = base + KVTILE_E;
        const __nv_bfloat16* Vh = base + 2 * KVTILE_E;
        const __nv_bfloat16* Vl = base + 3 * KVTILE_E;

        // ---- S = Q K^T ----
        float s[8][4];
#pragma unroll
        for (int f = 0; f < 8; f++)
#pragma unroll
            for (int e = 0; e < 4; e++) s[f][e] = 0.f;

        {
            const int g    = lane >> 3;
            const int brow = ((g >> 1) << 3) + (lane & 7);
            const int bcol = (g & 1) * 8;
#pragma unroll
            for (int kg = 0; kg < 4; kg++) {
#pragma unroll
                for (int np = 0; np < 2; np++) {       // nf2 pairs of 2
                    uint32_t kh[2][4], kl[2][4];
#pragma unroll
                    for (int u = 0; u < 2; u++) {
                        int nf2 = np * 2 + u;
                        uint32_t off = (uint32_t)((nf2 * 16 + brow) * LDA_A + kg * 16 + bcol);
                        ldx4(kh[u], smem_u32(Kh + off));
                        ldx4(kl[u], smem_u32(Kl + off));
                    }
                    // product-outermost: 4 distinct accs between reuse
#pragma unroll
                    for (int p = 0; p < 3; p++)
#pragma unroll
                        for (int u = 0; u < 2; u++)
#pragma unroll
                            for (int j = 0; j < 2; j++) {
                                float* d = s[(np * 2 + u) * 2 + j];
                                const uint32_t* av = (p == 2) ? ql[kg] : qh[kg];
                                const uint32_t* bv = (p == 1) ? &kl[u][j * 2]
                                                              : &kh[u][j * 2];
                                mma_bf16(d, av, bv);
                            }
                }
            }
        }

        // ---- scale + causal mask ----
        const bool needmask = (k0 + 63 > q0 + wq);
#pragma unroll
        for (int f = 0; f < 8; f++) {
#pragma unroll
            for (int e = 0; e < 4; e++) {
                float v = s[f][e] * 0.125f;
                if (needmask) {
                    int qi = q0 + wq + r0 + (e >> 1) * 8;
                    int ki = k0 + f * 8 + (lane & 3) * 2 + (e & 1);
                    v = (ki > qi) ? -1e30f : v;
                }
                s[f][e] = v;
            }
        }

        // ---- online softmax (rows r0, r0+8) ----
#pragma unroll
        for (int r = 0; r < 2; r++) {
            float vmax = -1e30f;
#pragma unroll
            for (int f = 0; f < 8; f++)
                vmax = fmaxf(vmax, fmaxf(s[f][2 * r], s[f][2 * r + 1]));
            vmax = fmaxf(vmax, __shfl_xor_sync(0xffffffffu, vmax, 1));
            vmax = fmaxf(vmax, __shfl_xor_sync(0xffffffffu, vmax, 2));
            float nm = fmaxf(m[r], vmax);
            float alpha = __expf(m[r] - nm);
            m[r] = nm;
            float rs = 0.f;
#pragma unroll
            for (int f = 0; f < 8; f++) {
                float p0 = __expf(s[f][2 * r] - nm);
                float p1 = __expf(s[f][2 * r + 1] - nm);
                s[f][2 * r] = p0; s[f][2 * r + 1] = p1;
                rs += p0 + p1;
            }
            rs += __shfl_xor_sync(0xffffffffu, rs, 1);
            rs += __shfl_xor_sync(0xffffffffu, rs, 2);
            lsum[r] = lsum[r] * alpha + rs;
#pragma unroll
            for (int f = 0; f < 8; f++) {
                O[f][2 * r] *= alpha;
                O[f][2 * r + 1] *= alpha;
            }
        }

        // ---- O += P V ----
        {
            const int g = lane >> 3;
            const int vrow = (g & 1) * 8 + (lane & 7);
            const int vcolb = (g >> 1) * 8;
#pragma unroll
            for (int kg = 0; kg < 4; kg++) {
                uint32_t pa_h[4], pa_l[4];
                pack_hilo(s[2 * kg][0],     s[2 * kg][1],     pa_h[0], pa_l[0]);
                pack_hilo(s[2 * kg][2],     s[2 * kg][3],     pa_h[1], pa_l[1]);
                pack_hilo(s[2 * kg + 1][0], s[2 * kg + 1][1], pa_h[2], pa_l[2]);
                pack_hilo(s[2 * kg + 1][2], s[2 * kg + 1][3], pa_h[3], pa_l[3]);
#pragma unroll
                for (int np = 0; np < 2; np++) {
                    uint32_t vh[2][4], vl[2][4];
#pragma unroll
                    for (int u = 0; u < 2; u++) {
                        int nf2 = np * 2 + u;
                        uint32_t off = (uint32_t)((kg * 16 + vrow) * LDA_A + nf2 * 16 + vcolb);
                        ldx4t(vh[u], smem_u32(Vh + off));
                        ldx4t(vl[u], smem_u32(Vl + off));
                    }
#pragma unroll
                    for (int p = 0; p < 3; p++)
#pragma unroll
                        for (int u = 0; u < 2; u++)
#pragma unroll
                            for (int j = 0; j < 2; j++) {
                                float* d = O[(np * 2 + u) * 2 + j];
                                const uint32_t* av = (p == 2) ? pa_l : pa_h;
                                const uint32_t* bv = (p == 1) ? &vl[u][j * 2]
                                                              : &vh[u][j * 2];
                                mma_bf16(d, av, bv);
                            }
                }
            }
        }
        __syncthreads();   // all warps done with KV[jb&1] before overwrite
    }

    // ---- normalize + write hi/lo bf16 output [token, C] ----
    const float inv0 = 1.0f / lsum[0];
    const float inv1 = 1.0f / lsum[1];
#pragma unroll
    for (int f = 0; f < 8; f++) {
        int col = h * D_ + f * 8 + (lane & 3) * 2;
        size_t row0 = (tok0 + q0 + wq + r0) * C_ + col;
        size_t row1 = (tok0 + q0 + wq + r0 + 8) * C_ + col;
        uint32_t hh, ll;
        pack_hilo(O[f][0] * inv0, O[f][1] * inv0, hh, ll);
        *(uint32_t*)&Yhi[row0] = hh;
        *(uint32_t*)&Ylo[row0] = ll;
        pack_hilo(O[f][2] * inv1, O[f][3] * inv1, hh, ll);
        *(uint32_t*)&Yhi[row1] = hh;
        *(uint32_t*)&Ylo[row1] = ll;
    }
}

// ---------------------------------------------------------------------------

extern "C" void kernel_launch(void* const* d_in, const int* in_sizes, int n_in,
                              void* d_out, int out_size)
{
    const float* x      = (const float*)d_in[0];   // [4,2048,1024]
    const float* w_attn = (const float*)d_in[1];   // [1024,3072]
    const float* w_proj = (const float*)d_in[2];   // [1024,1024]
    float* out = (float*)d_out;                    // [4,2048,1024]

    __nv_bfloat16 *ahi, *alo, *bhi, *blo, *shi, *slo;
    cudaGetSymbolAddress((void**)&ahi, g_Ahi);
    cudaGetSymbolAddress((void**)&alo, g_Alo);
    cudaGetSymbolAddress((void**)&bhi, g_Bhi);
    cudaGetSymbolAddress((void**)&blo, g_Blo);
    cudaGetSymbolAddress((void**)&shi, g_Shi);
    cudaGetSymbolAddress((void**)&slo, g_Slo);

    cudaFuncSetAttribute(gemm_mma_bf16x3<0>,
                         cudaFuncAttributeMaxDynamicSharedMemorySize, SMEM_GEMM);
    cudaFuncSetAttribute(gemm_mma_bf16x3<1>,
                         cudaFuncAttributeMaxDynamicSharedMemorySize, SMEM_GEMM);
    cudaFuncSetAttribute(attn_mma,
                         cudaFuncAttributeMaxDynamicSharedMemorySize, ATTN_SMEM);

    const int nA = MTOK * C_;

    // 1) split x -> bf16 hi/lo ; transpose+split w_attn -> [3C, C]
    cvt_hilo<<<nA / 4 / 256, 256>>>(x, ahi, alo, nA);
    cvt_w_t<<<dim3(3 * C_ / 32, C_ / 32), 256>>>(w_attn, bhi, blo, C_, 3 * C_);

    // 2) QKV GEMM -> hi/lo bf16 QKV directly
    gemm_mma_bf16x3<1><<<dim3(3 * C_ / 128, MTOK / 128), 256, SMEM_GEMM>>>(
        ahi, alo, bhi, blo, nullptr, shi, slo, 3 * C_, C_);

    // 3) tensor-core causal flash attention -> hi/lo bf16 into proj input bufs
    attn_mma<<<dim3(L_ / 128, H_, B_), 256, ATTN_SMEM>>>(shi, slo, ahi, alo);

    // 4) transpose+split w_proj
    cvt_w_t<<<dim3(C_ / 32, C_ / 32), 256>>>(w_proj, bhi, blo, C_, C_);

    // 5) proj GEMM -> fp32 out
    gemm_mma_bf16x3<0><<<dim3(C_ / 128, MTOK / 128), 256, SMEM_GEMM>>>(
        ahi, alo, bhi, blo, out, nullptr, nullptr, C_, C_);
}

// round 12
// speedup vs baseline: 1.1426x; 1.1426x over previous
#include <cuda_runtime.h>
#include <cuda_bf16.h>
#include <cstdint>

#define B_ 4
#define L_ 2048
#define C_ 1024
#define H_ 16
#define D_ 64
#define MTOK (B_ * L_)   // 8192 token rows

// ---------------------------------------------------------------------------
// Scratch (allocation-free rule: __device__ globals)
// ---------------------------------------------------------------------------
__device__ __nv_bfloat16 g_Ahi[(size_t)MTOK * C_];     // activation hi  [M,K]
__device__ __nv_bfloat16 g_Alo[(size_t)MTOK * C_];     // activation lo  [M,K]
__device__ __nv_bfloat16 g_Bhi[(size_t)3 * C_ * C_];   // weight^T hi    [N,K]
__device__ __nv_bfloat16 g_Blo[(size_t)3 * C_ * C_];   // weight^T lo    [N,K]
__device__ __nv_bfloat16 g_Shi[(size_t)MTOK * 3 * C_]; // QKV hi [8192,3072]
__device__ __nv_bfloat16 g_Slo[(size_t)MTOK * 3 * C_]; // QKV lo

// ---------------------------------------------------------------------------
// helpers
// ---------------------------------------------------------------------------
__device__ __forceinline__ uint32_t smem_u32(const void* p) {
    return (uint32_t)__cvta_generic_to_shared(p);
}
__device__ __forceinline__ void cp16(void* s, const void* g) {
    uint32_t sa = smem_u32(s);
    asm volatile("cp.async.cg.shared.global [%0], [%1], 16;" :: "r"(sa), "l"(g) : "memory");
}
__device__ __forceinline__ void ldx4(uint32_t* r, uint32_t addr) {
    asm volatile("ldmatrix.sync.aligned.m8n8.x4.shared.b16 {%0,%1,%2,%3}, [%4];"
                 : "=r"(r[0]), "=r"(r[1]), "=r"(r[2]), "=r"(r[3]) : "r"(addr));
}
__device__ __forceinline__ void ldx4t(uint32_t* r, uint32_t addr) {
    asm volatile("ldmatrix.sync.aligned.m8n8.x4.trans.shared.b16 {%0,%1,%2,%3}, [%4];"
                 : "=r"(r[0]), "=r"(r[1]), "=r"(r[2]), "=r"(r[3]) : "r"(addr));
}
__device__ __forceinline__ void mma_bf16(float* d, const uint32_t* a, const uint32_t* b) {
    asm volatile(
        "mma.sync.aligned.m16n8k16.row.col.f32.bf16.bf16.f32 "
        "{%0,%1,%2,%3}, {%4,%5,%6,%7}, {%8,%9}, {%0,%1,%2,%3};"
        : "+f"(d[0]), "+f"(d[1]), "+f"(d[2]), "+f"(d[3])
        : "r"(a[0]), "r"(a[1]), "r"(a[2]), "r"(a[3]), "r"(b[0]), "r"(b[1]));
}
// pack two floats into bf16x2 hi + bf16x2 lo (residual)
__device__ __forceinline__ void pack_hilo(float a, float b, uint32_t& h, uint32_t& l) {
    __nv_bfloat162 hv = __floats2bfloat162_rn(a, b);
    float2 hf = __bfloat1622float2(hv);
    __nv_bfloat162 lv = __floats2bfloat162_rn(a - hf.x, b - hf.y);
    h = *(uint32_t*)&hv;
    l = *(uint32_t*)&lv;
}

// ---------------------------------------------------------------------------
// fp32 -> bf16 hi/lo split (same layout)
// ---------------------------------------------------------------------------
__global__ __launch_bounds__(256) void cvt_hilo(
    const float* __restrict__ in, __nv_bfloat16* __restrict__ hi,
    __nv_bfloat16* __restrict__ lo, int n)
{
    int i = (blockIdx.x * 256 + threadIdx.x) * 4;
    if (i >= n) return;
    float4 v = *(const float4*)(in + i);
    float f[4] = {v.x, v.y, v.z, v.w};
    __align__(8) __nv_bfloat16 hb[4];
    __align__(8) __nv_bfloat16 lb[4];
#pragma unroll
    for (int j = 0; j < 4; j++) {
        hb[j] = __float2bfloat16(f[j]);
        lb[j] = __float2bfloat16(f[j] - __bfloat162float(hb[j]));
    }
    *(uint2*)(hi + i) = *(uint2*)hb;
    *(uint2*)(lo + i) = *(uint2*)lb;
}

// ---------------------------------------------------------------------------
// W [K,N] fp32 row-major -> W^T hi/lo bf16 [N,K]
// ---------------------------------------------------------------------------
__global__ __launch_bounds__(256) void cvt_w_t(
    const float* __restrict__ W, __nv_bfloat16* __restrict__ Thi,
    __nv_bfloat16* __restrict__ Tlo, int K, int N)
{
    __shared__ float tile[32][33];
    const int n0 = blockIdx.x * 32, k0 = blockIdx.y * 32;
    const int tx = threadIdx.x & 31, ty = threadIdx.x >> 5;   // 32 x 8
#pragma unroll
    for (int r = 0; r < 4; r++)
        tile[ty + 8 * r][tx] = W[(size_t)(k0 + ty + 8 * r) * N + n0 + tx];
    __syncthreads();
#pragma unroll
    for (int r = 0; r < 4; r++) {
        int n = n0 + ty + 8 * r;
        float v = tile[tx][ty + 8 * r];
        __nv_bfloat16 h = __float2bfloat16(v);
        __nv_bfloat16 l = __float2bfloat16(v - __bfloat162float(h));
        Thi[(size_t)n * K + k0 + tx] = h;
        Tlo[(size_t)n * K + k0 + tx] = l;
    }
}

// ---------------------------------------------------------------------------
// mma.sync bf16x3 GEMM: C[M,N] = A[M,K] @ B^T  (A [M,K], B [N,K], hi/lo bf16)
// CTA: 128x128 tile, BK=64, 256 threads (8 warps, 2Mx4N, warp tile 64x32),
// cp.async double-buffered, ONE __syncthreads per k-chunk:
//   wait(loads c) -> sync -> issue loads(c+1) -> compute(c)
// (the sync at the top of iter c+1 protects buffer (c+1)&1 from overwrite).
// MODE 0: fp32 out; MODE 1: hi/lo bf16 out.
// ---------------------------------------------------------------------------
#define BK_G   64
#define LDT    72                       // 64 + 8 pad (bf16 elems) -> 144B rows
#define MAT_B  (128 * LDT * 2)          // 18432 B per matrix (128 rows)
#define BUF_B  (4 * MAT_B)              // Ahi Alo Bhi Blo = 73728 B
#define SMEM_GEMM (2 * BUF_B)           // 147456 B

template<int MODE>
__global__ __launch_bounds__(256, 1)
void gemm_mma_bf16x3(const __nv_bfloat16* __restrict__ Ahi,
                     const __nv_bfloat16* __restrict__ Alo,
                     const __nv_bfloat16* __restrict__ Bhi,
                     const __nv_bfloat16* __restrict__ Blo,
                     float* __restrict__ Cf,
                     __nv_bfloat16* __restrict__ Chi,
                     __nv_bfloat16* __restrict__ Clo,
                     int N, int K)
{
    extern __shared__ __align__(128) char smem[];
    const int t    = threadIdx.x;
    const int lane = t & 31;
    const int wid  = t >> 5;
    const int bn   = blockIdx.x * 128;
    const int bm   = blockIdx.y * 128;
    const int wm   = (wid & 1) * 64;
    const int wn   = (wid >> 1) * 32;

    float acc[4][4][4];
#pragma unroll
    for (int i = 0; i < 4; i++)
#pragma unroll
        for (int j = 0; j < 4; j++)
#pragma unroll
            for (int r = 0; r < 4; r++) acc[i][j][r] = 0.f;

    const int nk = K / BK_G;   // 16

    auto load_tile = [&](int c, int buf) {
        char* bp = smem + buf * BUF_B;
        const int kc = c * BK_G;
#pragma unroll
        for (int i = 0; i < 4; i++) {
            int idx = t + 256 * i;
            int row = idx >> 3;            // 0..127
            int c16 = idx & 7;             // 16B chunk within 128B row
            uint32_t so = (uint32_t)(row * LDT + c16 * 8) * 2;
            size_t ga = (size_t)(bm + row) * K + kc + c16 * 8;
            size_t gb = (size_t)(bn + row) * K + kc + c16 * 8;
            cp16(bp + so,             Ahi + ga);
            cp16(bp + MAT_B + so,     Alo + ga);
            cp16(bp + 2 * MAT_B + so, Bhi + gb);
            cp16(bp + 3 * MAT_B + so, Blo + gb);
        }
    };

    load_tile(0, 0);
    asm volatile("cp.async.commit_group;" ::: "memory");

    for (int c = 0; c < nk; c++) {
        asm volatile("cp.async.wait_group 0;" ::: "memory");
        __syncthreads();                   // loads(c) visible; compute(c-1) drained
        if (c + 1 < nk) {
            load_tile(c + 1, (c + 1) & 1);
            asm volatile("cp.async.commit_group;" ::: "memory");
        }

        const char* bp = smem + (c & 1) * BUF_B;
        const __nv_bfloat16* sAhi = (const __nv_bfloat16*)(bp);
        const __nv_bfloat16* sAlo = (const __nv_bfloat16*)(bp + MAT_B);
        const __nv_bfloat16* sBhi = (const __nv_bfloat16*)(bp + 2 * MAT_B);
        const __nv_bfloat16* sBlo = (const __nv_bfloat16*)(bp + 3 * MAT_B);

#pragma unroll
        for (int ks = 0; ks < BK_G; ks += 16) {
            uint32_t ah[4][4], al[4][4], bh[2][4], bl[2][4];
            const int arow = lane & 15;
            const int acol = ks + (lane >> 4) * 8;
#pragma unroll
            for (int mf = 0; mf < 4; mf++) {
                uint32_t off = (uint32_t)((wm + mf * 16 + arow) * LDT + acol);
                ldx4(ah[mf], smem_u32(sAhi + off));
                ldx4(al[mf], smem_u32(sAlo + off));
            }
            const int g    = lane >> 3;
            const int brow = ((g >> 1) << 3) + (lane & 7);
            const int bcol = ks + (g & 1) * 8;
#pragma unroll
            for (int nf2 = 0; nf2 < 2; nf2++) {
                uint32_t off = (uint32_t)((wn + nf2 * 16 + brow) * LDT + bcol);
                ldx4(bh[nf2], smem_u32(sBhi + off));
                ldx4(bl[nf2], smem_u32(sBlo + off));
            }
#pragma unroll
            for (int p = 0; p < 3; p++)
#pragma unroll
                for (int mf = 0; mf < 4; mf++)
#pragma unroll
                    for (int nf2 = 0; nf2 < 2; nf2++)
#pragma unroll
                        for (int j = 0; j < 2; j++) {
                            const uint32_t* av = (p == 2) ? al[mf] : ah[mf];
                            const uint32_t* bv = (p == 1) ? &bl[nf2][j * 2]
                                                          : &bh[nf2][j * 2];
                            mma_bf16(acc[mf][nf2 * 2 + j], av, bv);
                        }
        }
    }

#pragma unroll
    for (int mf = 0; mf < 4; mf++)
#pragma unroll
        for (int nf = 0; nf < 4; nf++) {
            int row = bm + wm + mf * 16 + (lane >> 2);
            int col = bn + wn + nf * 8 + (lane & 3) * 2;
            if (MODE == 0) {
                *(float2*)&Cf[(size_t)row * N + col] =
                    make_float2(acc[mf][nf][0], acc[mf][nf][1]);
                *(float2*)&Cf[(size_t)(row + 8) * N + col] =
                    make_float2(acc[mf][nf][2], acc[mf][nf][3]);
            } else {
                uint32_t h, l;
                pack_hilo(acc[mf][nf][0], acc[mf][nf][1], h, l);
                *(uint32_t*)&Chi[(size_t)row * N + col] = h;
                *(uint32_t*)&Clo[(size_t)row * N + col] = l;
                pack_hilo(acc[mf][nf][2], acc[mf][nf][3], h, l);
                *(uint32_t*)&Chi[(size_t)(row + 8) * N + col] = h;
                *(uint32_t*)&Clo[(size_t)(row + 8) * N + col] = l;
            }
        }
}

// ---------------------------------------------------------------------------
// Tensor-core flash attention (bf16x3 hi/lo, fp32 accum) — R10 shape (measured
// 330us): CTA 128 threads (4 warps), 64-q tile, 64-k blocks, 2048 CTAs.
// ---------------------------------------------------------------------------
#define LDA_A 72
#define TILE_E (64 * LDA_A)                 // elems per smem matrix
#define ATTN_SMEM (6 * TILE_E * 2)          // Qh Ql Kh Kl Vh Vl = 55296 B

__global__ __launch_bounds__(128) void attn_mma(
    const __nv_bfloat16* __restrict__ Shi, const __nv_bfloat16* __restrict__ Slo,
    __nv_bfloat16* __restrict__ Yhi, __nv_bfloat16* __restrict__ Ylo)
{
    extern __shared__ __align__(16) char smraw[];
    __nv_bfloat16* Qh = (__nv_bfloat16*)smraw;
    __nv_bfloat16* Ql = Qh + TILE_E;
    __nv_bfloat16* Kh = Ql + TILE_E;
    __nv_bfloat16* Kl = Kh + TILE_E;
    __nv_bfloat16* Vh = Kl + TILE_E;
    __nv_bfloat16* Vl = Vh + TILE_E;

    const int it = blockIdx.x;          // q-tile (0..31)
    const int h  = blockIdx.y;
    const int b  = blockIdx.z;
    const int t  = threadIdx.x;
    const int lane = t & 31;
    const int wid  = t >> 5;
    const int wq   = wid * 16;          // warp's q-row offset in tile

    const int q0   = it * 64;
    const size_t tok0 = (size_t)b * L_;
    const int qcol = h * D_;
    const int kcol = C_ + h * D_;
    const int vcol = 2 * C_ + h * D_;

    // ---- stage Q tile (hi/lo), 64 rows x 128B each ----
#pragma unroll
    for (int i = 0; i < 4; i++) {
        int idx = t + 128 * i;
        int row = idx >> 3;
        int ch  = (idx & 7) * 8;
        size_t g = (tok0 + q0 + row) * (3 * C_) + qcol + ch;
        cp16(Qh + row * LDA_A + ch, Shi + g);
        cp16(Ql + row * LDA_A + ch, Slo + g);
    }
    asm volatile("cp.async.commit_group;" ::: "memory");
    asm volatile("cp.async.wait_group 0;" ::: "memory");
    __syncthreads();

    // ---- Q fragments (A-frags, m16k16 x 4 kgroups, hi+lo) ----
    uint32_t qh[4][4], ql[4][4];
    {
        const int arow = lane & 15;
        const int acol = (lane >> 4) * 8;
#pragma unroll
        for (int kg = 0; kg < 4; kg++) {
            uint32_t off = (uint32_t)((wq + arow) * LDA_A + kg * 16 + acol);
            ldx4(qh[kg], smem_u32(Qh + off));
            ldx4(ql[kg], smem_u32(Ql + off));
        }
    }

    const int r0 = lane >> 2;           // row pair within m16
    float m[2] = {-1e30f, -1e30f};
    float lsum[2] = {0.f, 0.f};
    float O[8][4];
#pragma unroll
    for (int f = 0; f < 8; f++)
#pragma unroll
        for (int e = 0; e < 4; e++) O[f][e] = 0.f;

    for (int jb = 0; jb <= it; jb++) {
        const int k0 = jb * 64;
        __syncthreads();   // all warps done with previous K/V tiles

        // ---- stage K/V tiles (hi/lo) ----
#pragma unroll
        for (int i = 0; i < 4; i++) {
            int idx = t + 128 * i;
            int row = idx >> 3;
            int ch  = (idx & 7) * 8;
            size_t gk = (tok0 + k0 + row) * (3 * C_) + kcol + ch;
            size_t gv = (tok0 + k0 + row) * (3 * C_) + vcol + ch;
            uint32_t so = row * LDA_A + ch;
            cp16(Kh + so, Shi + gk);
            cp16(Kl + so, Slo + gk);
            cp16(Vh + so, Shi + gv);
            cp16(Vl + so, Slo + gv);
        }
        asm volatile("cp.async.commit_group;" ::: "memory");
        asm volatile("cp.async.wait_group 0;" ::: "memory");
        __syncthreads();

        // ---- S = Q K^T (scores frags: 8 x n8) ----
        float s[8][4];
#pragma unroll
        for (int f = 0; f < 8; f++)
#pragma unroll
            for (int e = 0; e < 4; e++) s[f][e] = 0.f;

        {
            const int g    = lane >> 3;
            const int brow = ((g >> 1) << 3) + (lane & 7);
            const int bcol = (g & 1) * 8;
#pragma unroll
            for (int kg = 0; kg < 4; kg++) {
#pragma unroll
                for (int nf2 = 0; nf2 < 4; nf2++) {
                    uint32_t kh[4], kl[4];
                    uint32_t off = (uint32_t)((nf2 * 16 + brow) * LDA_A + kg * 16 + bcol);
                    ldx4(kh, smem_u32(Kh + off));
                    ldx4(kl, smem_u32(Kl + off));
#pragma unroll
                    for (int j = 0; j < 2; j++) {
                        float* d = s[nf2 * 2 + j];
                        mma_bf16(d, qh[kg], &kh[j * 2]);
                        mma_bf16(d, qh[kg], &kl[j * 2]);
                        mma_bf16(d, ql[kg], &kh[j * 2]);
                    }
                }
            }
        }

        // ---- scale + causal mask ----
        const bool diag = (jb == it);
#pragma unroll
        for (int f = 0; f < 8; f++) {
#pragma unroll
            for (int e = 0; e < 4; e++) {
                int qi = q0 + wq + r0 + (e >> 1) * 8;
                int ki = k0 + f * 8 + (lane & 3) * 2 + (e & 1);
                float v = s[f][e] * 0.125f;
                s[f][e] = (diag && ki > qi) ? -1e30f : v;
            }
        }

        // ---- online softmax (rows r0, r0+8) ----
#pragma unroll
        for (int r = 0; r < 2; r++) {
            float vmax = -1e30f;
#pragma unroll
            for (int f = 0; f < 8; f++)
                vmax = fmaxf(vmax, fmaxf(s[f][2 * r], s[f][2 * r + 1]));
            vmax = fmaxf(vmax, __shfl_xor_sync(0xffffffffu, vmax, 1));
            vmax = fmaxf(vmax, __shfl_xor_sync(0xffffffffu, vmax, 2));
            float nm = fmaxf(m[r], vmax);
            float alpha = __expf(m[r] - nm);
            m[r] = nm;
            float rs = 0.f;
#pragma unroll
            for (int f = 0; f < 8; f++) {
                float p0 = __expf(s[f][2 * r] - nm);
                float p1 = __expf(s[f][2 * r + 1] - nm);
                s[f][2 * r] = p0; s[f][2 * r + 1] = p1;
                rs += p0 + p1;
            }
            rs += __shfl_xor_sync(0xffffffffu, rs, 1);
            rs += __shfl_xor_sync(0xffffffffu, rs, 2);
            lsum[r] = lsum[r] * alpha + rs;
#pragma unroll
            for (int f = 0; f < 8; f++) {
                O[f][2 * r] *= alpha;
                O[f][2 * r + 1] *= alpha;
            }
        }

        // ---- O += P V (P packed from score frags; V via ldmatrix.trans) ----
        {
            const int g = lane >> 3;
            const int vrow = (g & 1) * 8 + (lane & 7);
            const int vcolb = (g >> 1) * 8;
#pragma unroll
            for (int kg = 0; kg < 4; kg++) {
                uint32_t pa_h[4], pa_l[4];
                pack_hilo(s[2 * kg][0],     s[2 * kg][1],     pa_h[0], pa_l[0]);
                pack_hilo(s[2 * kg][2],     s[2 * kg][3],     pa_h[1], pa_l[1]);
                pack_hilo(s[2 * kg + 1][0], s[2 * kg + 1][1], pa_h[2], pa_l[2]);
                pack_hilo(s[2 * kg + 1][2], s[2 * kg + 1][3], pa_h[3], pa_l[3]);
#pragma unroll
                for (int nf2 = 0; nf2 < 4; nf2++) {
                    uint32_t vh[4], vl[4];
                    uint32_t off = (uint32_t)((kg * 16 + vrow) * LDA_A + nf2 * 16 + vcolb);
                    ldx4t(vh, smem_u32(Vh + off));
                    ldx4t(vl, smem_u32(Vl + off));
#pragma unroll
                    for (int j = 0; j < 2; j++) {
                        float* d = O[nf2 * 2 + j];
                        mma_bf16(d, pa_h, &vh[j * 2]);
                        mma_bf16(d, pa_h, &vl[j * 2]);
                        mma_bf16(d, pa_l, &vh[j * 2]);
                    }
                }
            }
        }
    }

    // ---- normalize + write hi/lo bf16 output [token, C] ----
    const float inv0 = 1.0f / lsum[0];
    const float inv1 = 1.0f / lsum[1];
#pragma unroll
    for (int f = 0; f < 8; f++) {
        int col = h * D_ + f * 8 + (lane & 3) * 2;
        size_t row0 = (tok0 + q0 + wq + r0) * C_ + col;
        size_t row1 = (tok0 + q0 + wq + r0 + 8) * C_ + col;
        uint32_t hh, ll;
        pack_hilo(O[f][0] * inv0, O[f][1] * inv0, hh, ll);
        *(uint32_t*)&Yhi[row0] = hh;
        *(uint32_t*)&Ylo[row0] = ll;
        pack_hilo(O[f][2] * inv1, O[f][3] * inv1, hh, ll);
        *(uint32_t*)&Yhi[row1] = hh;
        *(uint32_t*)&Ylo[row1] = ll;
    }
}

// ---------------------------------------------------------------------------

extern "C" void kernel_launch(void* const* d_in, const int* in_sizes, int n_in,
                              void* d_out, int out_size)
{
    const float* x      = (const float*)d_in[0];   // [4,2048,1024]
    const float* w_attn = (const float*)d_in[1];   // [1024,3072]
    const float* w_proj = (const float*)d_in[2];   // [1024,1024]
    float* out = (float*)d_out;                    // [4,2048,1024]

    __nv_bfloat16 *ahi, *alo, *bhi, *blo, *shi, *slo;
    cudaGetSymbolAddress((void**)&ahi, g_Ahi);
    cudaGetSymbolAddress((void**)&alo, g_Alo);
    cudaGetSymbolAddress((void**)&bhi, g_Bhi);
    cudaGetSymbolAddress((void**)&blo, g_Blo);
    cudaGetSymbolAddress((void**)&shi, g_Shi);
    cudaGetSymbolAddress((void**)&slo, g_Slo);

    cudaFuncSetAttribute(gemm_mma_bf16x3<0>,
                         cudaFuncAttributeMaxDynamicSharedMemorySize, SMEM_GEMM);
    cudaFuncSetAttribute(gemm_mma_bf16x3<1>,
                         cudaFuncAttributeMaxDynamicSharedMemorySize, SMEM_GEMM);
    cudaFuncSetAttribute(attn_mma,
                         cudaFuncAttributeMaxDynamicSharedMemorySize, ATTN_SMEM);

    const int nA = MTOK * C_;

    // 1) split x -> bf16 hi/lo ; transpose+split w_attn -> [3C, C]
    cvt_hilo<<<nA / 4 / 256, 256>>>(x, ahi, alo, nA);
    cvt_w_t<<<dim3(3 * C_ / 32, C_ / 32), 256>>>(w_attn, bhi, blo, C_, 3 * C_);

    // 2) QKV GEMM -> hi/lo bf16 QKV directly
    gemm_mma_bf16x3<1><<<dim3(3 * C_ / 128, MTOK / 128), 256, SMEM_GEMM>>>(
        ahi, alo, bhi, blo, nullptr, shi, slo, 3 * C_, C_);

    // 3) tensor-core causal flash attention -> hi/lo bf16 into proj input bufs
    attn_mma<<<dim3(L_ / 64, H_, B_), 128, ATTN_SMEM>>>(shi, slo, ahi, alo);

    // 4) transpose+split w_proj
    cvt_w_t<<<dim3(C_ / 32, C_ / 32), 256>>>(w_proj, bhi, blo, C_, C_);

    // 5) proj GEMM -> fp32 out
    gemm_mma_bf16x3<0><<<dim3(C_ / 128, MTOK / 128), 256, SMEM_GEMM>>>(
        ahi, alo, bhi, blo, out, nullptr, nullptr, C_, C_);
}

// round 13
// speedup vs baseline: 1.1601x; 1.0153x over previous
#include <cuda_runtime.h>
#include <cuda_bf16.h>
#include <cstdint>

#define B_ 4
#define L_ 2048
#define C_ 1024
#define H_ 16
#define D_ 64
#define MTOK (B_ * L_)   // 8192 token rows

// ---------------------------------------------------------------------------
// Scratch (allocation-free rule: __device__ globals)
// ---------------------------------------------------------------------------
__device__ __nv_bfloat16 g_Ahi[(size_t)MTOK * C_];     // activation hi  [M,K]
__device__ __nv_bfloat16 g_Alo[(size_t)MTOK * C_];     // activation lo  [M,K]
__device__ __nv_bfloat16 g_Bhi[(size_t)3 * C_ * C_];   // weight^T hi    [N,K]
__device__ __nv_bfloat16 g_Blo[(size_t)3 * C_ * C_];   // weight^T lo    [N,K]
__device__ __nv_bfloat16 g_Shi[(size_t)MTOK * 3 * C_]; // QKV hi [8192,3072]
__device__ __nv_bfloat16 g_Slo[(size_t)MTOK * 3 * C_]; // QKV lo

// ---------------------------------------------------------------------------
// helpers
// ---------------------------------------------------------------------------
__device__ __forceinline__ uint32_t smem_u32(const void* p) {
    return (uint32_t)__cvta_generic_to_shared(p);
}
__device__ __forceinline__ void cp16(void* s, const void* g) {
    uint32_t sa = smem_u32(s);
    asm volatile("cp.async.cg.shared.global [%0], [%1], 16;" :: "r"(sa), "l"(g) : "memory");
}
__device__ __forceinline__ void ldx4(uint32_t* r, uint32_t addr) {
    asm volatile("ldmatrix.sync.aligned.m8n8.x4.shared.b16 {%0,%1,%2,%3}, [%4];"
                 : "=r"(r[0]), "=r"(r[1]), "=r"(r[2]), "=r"(r[3]) : "r"(addr));
}
__device__ __forceinline__ void ldx4t(uint32_t* r, uint32_t addr) {
    asm volatile("ldmatrix.sync.aligned.m8n8.x4.trans.shared.b16 {%0,%1,%2,%3}, [%4];"
                 : "=r"(r[0]), "=r"(r[1]), "=r"(r[2]), "=r"(r[3]) : "r"(addr));
}
__device__ __forceinline__ void mma_bf16(float* d, const uint32_t* a, const uint32_t* b) {
    asm volatile(
        "mma.sync.aligned.m16n8k16.row.col.f32.bf16.bf16.f32 "
        "{%0,%1,%2,%3}, {%4,%5,%6,%7}, {%8,%9}, {%0,%1,%2,%3};"
        : "+f"(d[0]), "+f"(d[1]), "+f"(d[2]), "+f"(d[3])
        : "r"(a[0]), "r"(a[1]), "r"(a[2]), "r"(a[3]), "r"(b[0]), "r"(b[1]));
}
// pack two floats into bf16x2 hi + bf16x2 lo (residual)
__device__ __forceinline__ void pack_hilo(float a, float b, uint32_t& h, uint32_t& l) {
    __nv_bfloat162 hv = __floats2bfloat162_rn(a, b);
    float2 hf = __bfloat1622float2(hv);
    __nv_bfloat162 lv = __floats2bfloat162_rn(a - hf.x, b - hf.y);
    h = *(uint32_t*)&hv;
    l = *(uint32_t*)&lv;
}

// ---------------------------------------------------------------------------
// fp32 -> bf16 hi/lo split (same layout)
// ---------------------------------------------------------------------------
__global__ __launch_bounds__(256) void cvt_hilo(
    const float* __restrict__ in, __nv_bfloat16* __restrict__ hi,
    __nv_bfloat16* __restrict__ lo, int n)
{
    int i = (blockIdx.x * 256 + threadIdx.x) * 4;
    if (i >= n) return;
    float4 v = *(const float4*)(in + i);
    float f[4] = {v.x, v.y, v.z, v.w};
    __align__(8) __nv_bfloat16 hb[4];
    __align__(8) __nv_bfloat16 lb[4];
#pragma unroll
    for (int j = 0; j < 4; j++) {
        hb[j] = __float2bfloat16(f[j]);
        lb[j] = __float2bfloat16(f[j] - __bfloat162float(hb[j]));
    }
    *(uint2*)(hi + i) = *(uint2*)hb;
    *(uint2*)(lo + i) = *(uint2*)lb;
}

// ---------------------------------------------------------------------------
// W [K,N] fp32 row-major -> W^T hi/lo bf16 [N,K]
// ---------------------------------------------------------------------------
__global__ __launch_bounds__(256) void cvt_w_t(
    const float* __restrict__ W, __nv_bfloat16* __restrict__ Thi,
    __nv_bfloat16* __restrict__ Tlo, int K, int N)
{
    __shared__ float tile[32][33];
    const int n0 = blockIdx.x * 32, k0 = blockIdx.y * 32;
    const int tx = threadIdx.x & 31, ty = threadIdx.x >> 5;   // 32 x 8
#pragma unroll
    for (int r = 0; r < 4; r++)
        tile[ty + 8 * r][tx] = W[(size_t)(k0 + ty + 8 * r) * N + n0 + tx];
    __syncthreads();
#pragma unroll
    for (int r = 0; r < 4; r++) {
        int n = n0 + ty + 8 * r;
        float v = tile[tx][ty + 8 * r];
        __nv_bfloat16 h = __float2bfloat16(v);
        __nv_bfloat16 l = __float2bfloat16(v - __bfloat162float(h));
        Thi[(size_t)n * K + k0 + tx] = h;
        Tlo[(size_t)n * K + k0 + tx] = l;
    }
}

// ---------------------------------------------------------------------------
// mma.sync bf16x3 GEMM: C[M,N] = A[M,K] @ B^T  (A [M,K], B [N,K], hi/lo bf16)
// CTA: 128x256 tile, BK=64, 256 threads (8 warps, 2Mx4N, warp tile 64x64),
// cp.async double-buffered, ONE __syncthreads per k-chunk.
// MODE 0: fp32 out; MODE 1: hi/lo bf16 out.
// ---------------------------------------------------------------------------
#define BK_G   64
#define LDT    72                        // 64 + 8 pad (bf16 elems) -> 144B rows
#define MAT_A  (128 * LDT * 2)           // 18432 B (A hi or lo, 128 rows)
#define MAT_Bb (256 * LDT * 2)           // 36864 B (B hi or lo, 256 rows)
#define BUF_B  (2 * MAT_A + 2 * MAT_Bb)  // 110592 B per stage
#define SMEM_GEMM (2 * BUF_B)            // 221184 B

template<int MODE>
__global__ __launch_bounds__(256, 1)
void gemm_mma_bf16x3(const __nv_bfloat16* __restrict__ Ahi,
                     const __nv_bfloat16* __restrict__ Alo,
                     const __nv_bfloat16* __restrict__ Bhi,
                     const __nv_bfloat16* __restrict__ Blo,
                     float* __restrict__ Cf,
                     __nv_bfloat16* __restrict__ Chi,
                     __nv_bfloat16* __restrict__ Clo,
                     int N, int K)
{
    extern __shared__ __align__(128) char smem[];
    const int t    = threadIdx.x;
    const int lane = t & 31;
    const int wid  = t >> 5;
    const int bn   = blockIdx.x * 256;
    const int bm   = blockIdx.y * 128;
    const int wm   = (wid & 1) * 64;      // 2 warps in M
    const int wn   = (wid >> 1) * 64;     // 4 warps in N

    float acc[4][8][4];
#pragma unroll
    for (int i = 0; i < 4; i++)
#pragma unroll
        for (int j = 0; j < 8; j++)
#pragma unroll
            for (int r = 0; r < 4; r++) acc[i][j][r] = 0.f;

    const int nk = K / BK_G;   // 16

    auto load_tile = [&](int c, int buf) {
        char* bp = smem + buf * BUF_B;
        const int kc = c * BK_G;
        // A hi/lo: 128 rows x 8 chunks of 16B
#pragma unroll
        for (int i = 0; i < 4; i++) {
            int idx = t + 256 * i;
            int row = idx >> 3;            // 0..127
            int c16 = idx & 7;
            uint32_t so = (uint32_t)(row * LDT + c16 * 8) * 2;
            size_t ga = (size_t)(bm + row) * K + kc + c16 * 8;
            cp16(bp + so,         Ahi + ga);
            cp16(bp + MAT_A + so, Alo + ga);
        }
        // B hi/lo: 256 rows x 8 chunks of 16B
#pragma unroll
        for (int i = 0; i < 8; i++) {
            int idx = t + 256 * i;
            int row = idx >> 3;            // 0..255
            int c16 = idx & 7;
            uint32_t so = (uint32_t)(row * LDT + c16 * 8) * 2;
            size_t gb = (size_t)(bn + row) * K + kc + c16 * 8;
            cp16(bp + 2 * MAT_A + so,          Bhi + gb);
            cp16(bp + 2 * MAT_A + MAT_Bb + so, Blo + gb);
        }
    };

    load_tile(0, 0);
    asm volatile("cp.async.commit_group;" ::: "memory");

    for (int c = 0; c < nk; c++) {
        asm volatile("cp.async.wait_group 0;" ::: "memory");
        __syncthreads();                   // loads(c) visible; compute(c-1) drained
        if (c + 1 < nk) {
            load_tile(c + 1, (c + 1) & 1);
            asm volatile("cp.async.commit_group;" ::: "memory");
        }

        const char* bp = smem + (c & 1) * BUF_B;
        const __nv_bfloat16* sAhi = (const __nv_bfloat16*)(bp);
        const __nv_bfloat16* sAlo = (const __nv_bfloat16*)(bp + MAT_A);
        const __nv_bfloat16* sBhi = (const __nv_bfloat16*)(bp + 2 * MAT_A);
        const __nv_bfloat16* sBlo = (const __nv_bfloat16*)(bp + 2 * MAT_A + MAT_Bb);

#pragma unroll
        for (int ks = 0; ks < BK_G; ks += 16) {
            uint32_t ah[4][4], al[4][4], bh[4][4], bl[4][4];
            const int arow = lane & 15;
            const int acol = ks + (lane >> 4) * 8;
#pragma unroll
            for (int mf = 0; mf < 4; mf++) {
                uint32_t off = (uint32_t)((wm + mf * 16 + arow) * LDT + acol);
                ldx4(ah[mf], smem_u32(sAhi + off));
                ldx4(al[mf], smem_u32(sAlo + off));
            }
            const int g    = lane >> 3;
            const int brow = ((g >> 1) << 3) + (lane & 7);
            const int bcol = ks + (g & 1) * 8;
#pragma unroll
            for (int nf2 = 0; nf2 < 4; nf2++) {
                uint32_t off = (uint32_t)((wn + nf2 * 16 + brow) * LDT + bcol);
                ldx4(bh[nf2], smem_u32(sBhi + off));
                ldx4(bl[nf2], smem_u32(sBlo + off));
            }
#pragma unroll
            for (int p = 0; p < 3; p++)
#pragma unroll
                for (int mf = 0; mf < 4; mf++)
#pragma unroll
                    for (int nf2 = 0; nf2 < 4; nf2++)
#pragma unroll
                        for (int j = 0; j < 2; j++) {
                            const uint32_t* av = (p == 2) ? al[mf] : ah[mf];
                            const uint32_t* bv = (p == 1) ? &bl[nf2][j * 2]
                                                          : &bh[nf2][j * 2];
                            mma_bf16(acc[mf][nf2 * 2 + j], av, bv);
                        }
        }
    }

#pragma unroll
    for (int mf = 0; mf < 4; mf++)
#pragma unroll
        for (int nf = 0; nf < 8; nf++) {
            int row = bm + wm + mf * 16 + (lane >> 2);
            int col = bn + wn + nf * 8 + (lane & 3) * 2;
            if (MODE == 0) {
                *(float2*)&Cf[(size_t)row * N + col] =
                    make_float2(acc[mf][nf][0], acc[mf][nf][1]);
                *(float2*)&Cf[(size_t)(row + 8) * N + col] =
                    make_float2(acc[mf][nf][2], acc[mf][nf][3]);
            } else {
                uint32_t h, l;
                pack_hilo(acc[mf][nf][0], acc[mf][nf][1], h, l);
                *(uint32_t*)&Chi[(size_t)row * N + col] = h;
                *(uint32_t*)&Clo[(size_t)row * N + col] = l;
                pack_hilo(acc[mf][nf][2], acc[mf][nf][3], h, l);
                *(uint32_t*)&Chi[(size_t)(row + 8) * N + col] = h;
                *(uint32_t*)&Clo[(size_t)(row + 8) * N + col] = l;
            }
        }
}

// ---------------------------------------------------------------------------
// Tensor-core flash attention (bf16x3 hi/lo, fp32 accum) — unchanged (322us):
// CTA 128 threads (4 warps), 64-q tile, 64-k blocks, 2048 CTAs.
// ---------------------------------------------------------------------------
#define LDA_A 72
#define TILE_E (64 * LDA_A)                 // elems per smem matrix
#define ATTN_SMEM (6 * TILE_E * 2)          // Qh Ql Kh Kl Vh Vl = 55296 B

__global__ __launch_bounds__(128) void attn_mma(
    const __nv_bfloat16* __restrict__ Shi, const __nv_bfloat16* __restrict__ Slo,
    __nv_bfloat16* __restrict__ Yhi, __nv_bfloat16* __restrict__ Ylo)
{
    extern __shared__ __align__(16) char smraw[];
    __nv_bfloat16* Qh = (__nv_bfloat16*)smraw;
    __nv_bfloat16* Ql = Qh + TILE_E;
    __nv_bfloat16* Kh = Ql + TILE_E;
    __nv_bfloat16* Kl = Kh + TILE_E;
    __nv_bfloat16* Vh = Kl + TILE_E;
    __nv_bfloat16* Vl = Vh + TILE_E;

    const int it = blockIdx.x;          // q-tile (0..31)
    const int h  = blockIdx.y;
    const int b  = blockIdx.z;
    const int t  = threadIdx.x;
    const int lane = t & 31;
    const int wid  = t >> 5;
    const int wq   = wid * 16;          // warp's q-row offset in tile

    const int q0   = it * 64;
    const size_t tok0 = (size_t)b * L_;
    const int qcol = h * D_;
    const int kcol = C_ + h * D_;
    const int vcol = 2 * C_ + h * D_;

    // ---- stage Q tile (hi/lo), 64 rows x 128B each ----
#pragma unroll
    for (int i = 0; i < 4; i++) {
        int idx = t + 128 * i;
        int row = idx >> 3;
        int ch  = (idx & 7) * 8;
        size_t g = (tok0 + q0 + row) * (3 * C_) + qcol + ch;
        cp16(Qh + row * LDA_A + ch, Shi + g);
        cp16(Ql + row * LDA_A + ch, Slo + g);
    }
    asm volatile("cp.async.commit_group;" ::: "memory");
    asm volatile("cp.async.wait_group 0;" ::: "memory");
    __syncthreads();

    // ---- Q fragments (A-frags, m16k16 x 4 kgroups, hi+lo) ----
    uint32_t qh[4][4], ql[4][4];
    {
        const int arow = lane & 15;
        const int acol = (lane >> 4) * 8;
#pragma unroll
        for (int kg = 0; kg < 4; kg++) {
            uint32_t off = (uint32_t)((wq + arow) * LDA_A + kg * 16 + acol);
            ldx4(qh[kg], smem_u32(Qh + off));
            ldx4(ql[kg], smem_u32(Ql + off));
        }
    }

    const int r0 = lane >> 2;           // row pair within m16
    float m[2] = {-1e30f, -1e30f};
    float lsum[2] = {0.f, 0.f};
    float O[8][4];
#pragma unroll
    for (int f = 0; f < 8; f++)
#pragma unroll
        for (int e = 0; e < 4; e++) O[f][e] = 0.f;

    for (int jb = 0; jb <= it; jb++) {
        const int k0 = jb * 64;
        __syncthreads();   // all warps done with previous K/V tiles

        // ---- stage K/V tiles (hi/lo) ----
#pragma unroll
        for (int i = 0; i < 4; i++) {
            int idx = t + 128 * i;
            int row = idx >> 3;
            int ch  = (idx & 7) * 8;
            size_t gk = (tok0 + k0 + row) * (3 * C_) + kcol + ch;
            size_t gv = (tok0 + k0 + row) * (3 * C_) + vcol + ch;
            uint32_t so = row * LDA_A + ch;
            cp16(Kh + so, Shi + gk);
            cp16(Kl + so, Slo + gk);
            cp16(Vh + so, Shi + gv);
            cp16(Vl + so, Slo + gv);
        }
        asm volatile("cp.async.commit_group;" ::: "memory");
        asm volatile("cp.async.wait_group 0;" ::: "memory");
        __syncthreads();

        // ---- S = Q K^T (scores frags: 8 x n8) ----
        float s[8][4];
#pragma unroll
        for (int f = 0; f < 8; f++)
#pragma unroll
            for (int e = 0; e < 4; e++) s[f][e] = 0.f;

        {
            const int g    = lane >> 3;
            const int brow = ((g >> 1) << 3) + (lane & 7);
            const int bcol = (g & 1) * 8;
#pragma unroll
            for (int kg = 0; kg < 4; kg++) {
#pragma unroll
                for (int nf2 = 0; nf2 < 4; nf2++) {
                    uint32_t kh[4], kl[4];
                    uint32_t off = (uint32_t)((nf2 * 16 + brow) * LDA_A + kg * 16 + bcol);
                    ldx4(kh, smem_u32(Kh + off));
                    ldx4(kl, smem_u32(Kl + off));
#pragma unroll
                    for (int j = 0; j < 2; j++) {
                        float* d = s[nf2 * 2 + j];
                        mma_bf16(d, qh[kg], &kh[j * 2]);
                        mma_bf16(d, qh[kg], &kl[j * 2]);
                        mma_bf16(d, ql[kg], &kh[j * 2]);
                    }
                }
            }
        }

        // ---- scale + causal mask ----
        const bool diag = (jb == it);
#pragma unroll
        for (int f = 0; f < 8; f++) {
#pragma unroll
            for (int e = 0; e < 4; e++) {
                int qi = q0 + wq + r0 + (e >> 1) * 8;
                int ki = k0 + f * 8 + (lane & 3) * 2 + (e & 1);
                float v = s[f][e] * 0.125f;
                s[f][e] = (diag && ki > qi) ? -1e30f : v;
            }
        }

        // ---- online softmax (rows r0, r0+8) ----
#pragma unroll
        for (int r = 0; r < 2; r++) {
            float vmax = -1e30f;
#pragma unroll
            for (int f = 0; f < 8; f++)
                vmax = fmaxf(vmax, fmaxf(s[f][2 * r], s[f][2 * r + 1]));
            vmax = fmaxf(vmax, __shfl_xor_sync(0xffffffffu, vmax, 1));
            vmax = fmaxf(vmax, __shfl_xor_sync(0xffffffffu, vmax, 2));
            float nm = fmaxf(m[r], vmax);
            float alpha = __expf(m[r] - nm);
            m[r] = nm;
            float rs = 0.f;
#pragma unroll
            for (int f = 0; f < 8; f++) {
                float p0 = __expf(s[f][2 * r] - nm);
                float p1 = __expf(s[f][2 * r + 1] - nm);
                s[f][2 * r] = p0; s[f][2 * r + 1] = p1;
                rs += p0 + p1;
            }
            rs += __shfl_xor_sync(0xffffffffu, rs, 1);
            rs += __shfl_xor_sync(0xffffffffu, rs, 2);
            lsum[r] = lsum[r] * alpha + rs;
#pragma unroll
            for (int f = 0; f < 8; f++) {
                O[f][2 * r] *= alpha;
                O[f][2 * r + 1] *= alpha;
            }
        }

        // ---- O += P V (P packed from score frags; V via ldmatrix.trans) ----
        {
            const int g = lane >> 3;
            const int vrow = (g & 1) * 8 + (lane & 7);
            const int vcolb = (g >> 1) * 8;
#pragma unroll
            for (int kg = 0; kg < 4; kg++) {
                uint32_t pa_h[4], pa_l[4];
                pack_hilo(s[2 * kg][0],     s[2 * kg][1],     pa_h[0], pa_l[0]);
                pack_hilo(s[2 * kg][2],     s[2 * kg][3],     pa_h[1], pa_l[1]);
                pack_hilo(s[2 * kg + 1][0], s[2 * kg + 1][1], pa_h[2], pa_l[2]);
                pack_hilo(s[2 * kg + 1][2], s[2 * kg + 1][3], pa_h[3], pa_l[3]);
#pragma unroll
                for (int nf2 = 0; nf2 < 4; nf2++) {
                    uint32_t vh[4], vl[4];
                    uint32_t off = (uint32_t)((kg * 16 + vrow) * LDA_A + nf2 * 16 + vcolb);
                    ldx4t(vh, smem_u32(Vh + off));
                    ldx4t(vl, smem_u32(Vl + off));
#pragma unroll
                    for (int j = 0; j < 2; j++) {
                        float* d = O[nf2 * 2 + j];
                        mma_bf16(d, pa_h, &vh[j * 2]);
                        mma_bf16(d, pa_h, &vl[j * 2]);
                        mma_bf16(d, pa_l, &vh[j * 2]);
                    }
                }
            }
        }
    }

    // ---- normalize + write hi/lo bf16 output [token, C] ----
    const float inv0 = 1.0f / lsum[0];
    const float inv1 = 1.0f / lsum[1];
#pragma unroll
    for (int f = 0; f < 8; f++) {
        int col = h * D_ + f * 8 + (lane & 3) * 2;
        size_t row0 = (tok0 + q0 + wq + r0) * C_ + col;
        size_t row1 = (tok0 + q0 + wq + r0 + 8) * C_ + col;
        uint32_t hh, ll;
        pack_hilo(O[f][0] * inv0, O[f][1] * inv0, hh, ll);
        *(uint32_t*)&Yhi[row0] = hh;
        *(uint32_t*)&Ylo[row0] = ll;
        pack_hilo(O[f][2] * inv1, O[f][3] * inv1, hh, ll);
        *(uint32_t*)&Yhi[row1] = hh;
        *(uint32_t*)&Ylo[row1] = ll;
    }
}

// ---------------------------------------------------------------------------

extern "C" void kernel_launch(void* const* d_in, const int* in_sizes, int n_in,
                              void* d_out, int out_size)
{
    const float* x      = (const float*)d_in[0];   // [4,2048,1024]
    const float* w_attn = (const float*)d_in[1];   // [1024,3072]
    const float* w_proj = (const float*)d_in[2];   // [1024,1024]
    float* out = (float*)d_out;                    // [4,2048,1024]

    __nv_bfloat16 *ahi, *alo, *bhi, *blo, *shi, *slo;
    cudaGetSymbolAddress((void**)&ahi, g_Ahi);
    cudaGetSymbolAddress((void**)&alo, g_Alo);
    cudaGetSymbolAddress((void**)&bhi, g_Bhi);
    cudaGetSymbolAddress((void**)&blo, g_Blo);
    cudaGetSymbolAddress((void**)&shi, g_Shi);
    cudaGetSymbolAddress((void**)&slo, g_Slo);

    cudaFuncSetAttribute(gemm_mma_bf16x3<0>,
                         cudaFuncAttributeMaxDynamicSharedMemorySize, SMEM_GEMM);
    cudaFuncSetAttribute(gemm_mma_bf16x3<1>,
                         cudaFuncAttributeMaxDynamicSharedMemorySize, SMEM_GEMM);
    cudaFuncSetAttribute(attn_mma,
                         cudaFuncAttributeMaxDynamicSharedMemorySize, ATTN_SMEM);

    const int nA = MTOK * C_;

    // 1) split x -> bf16 hi/lo ; transpose+split w_attn -> [3C, C]
    cvt_hilo<<<nA / 4 / 256, 256>>>(x, ahi, alo, nA);
    cvt_w_t<<<dim3(3 * C_ / 32, C_ / 32), 256>>>(w_attn, bhi, blo, C_, 3 * C_);

    // 2) QKV GEMM -> hi/lo bf16 QKV directly
    gemm_mma_bf16x3<1><<<dim3(3 * C_ / 256, MTOK / 128), 256, SMEM_GEMM>>>(
        ahi, alo, bhi, blo, nullptr, shi, slo, 3 * C_, C_);

    // 3) tensor-core causal flash attention -> hi/lo bf16 into proj input bufs
    attn_mma<<<dim3(L_ / 64, H_, B_), 128, ATTN_SMEM>>>(shi, slo, ahi, alo);

    // 4) transpose+split w_proj
    cvt_w_t<<<dim3(C_ / 32, C_ / 32), 256>>>(w_proj, bhi, blo, C_, C_);

    // 5) proj GEMM -> fp32 out
    gemm_mma_bf16x3<0><<<dim3(C_ / 256, MTOK / 128), 256, SMEM_GEMM>>>(
        ahi, alo, bhi, blo, out, nullptr, nullptr, C_, C_);
}

// round 14
// speedup vs baseline: 1.3364x; 1.1519x over previous
#include <cuda_runtime.h>
#include <cuda_fp16.h>
#include <cstdint>

#define B_ 4
#define L_ 2048
#define C_ 1024
#define H_ 16
#define D_ 64
#define MTOK (B_ * L_)   // 8192 token rows

// ---------------------------------------------------------------------------
// Scratch (allocation-free rule: __device__ globals)
// ---------------------------------------------------------------------------
__device__ __half g_Ahi[(size_t)MTOK * C_];     // activation hi  [M,K]
__device__ __half g_Alo[(size_t)MTOK * C_];     // activation lo  [M,K]
__device__ __half g_Bhi[(size_t)3 * C_ * C_];   // weight^T hi    [N,K]
__device__ __half g_Blo[(size_t)3 * C_ * C_];   // weight^T lo    [N,K]
__device__ __half g_Shi[(size_t)MTOK * 3 * C_]; // QKV hi [8192,3072]
__device__ __half g_Slo[(size_t)MTOK * 3 * C_]; // QKV lo

// ---------------------------------------------------------------------------
// helpers
// ---------------------------------------------------------------------------
__device__ __forceinline__ uint32_t smem_u32(const void* p) {
    return (uint32_t)__cvta_generic_to_shared(p);
}
__device__ __forceinline__ void cp16(void* s, const void* g) {
    uint32_t sa = smem_u32(s);
    asm volatile("cp.async.cg.shared.global [%0], [%1], 16;" :: "r"(sa), "l"(g) : "memory");
}
__device__ __forceinline__ void ldx4(uint32_t* r, uint32_t addr) {
    asm volatile("ldmatrix.sync.aligned.m8n8.x4.shared.b16 {%0,%1,%2,%3}, [%4];"
                 : "=r"(r[0]), "=r"(r[1]), "=r"(r[2]), "=r"(r[3]) : "r"(addr));
}
__device__ __forceinline__ void ldx4t(uint32_t* r, uint32_t addr) {
    asm volatile("ldmatrix.sync.aligned.m8n8.x4.trans.shared.b16 {%0,%1,%2,%3}, [%4];"
                 : "=r"(r[0]), "=r"(r[1]), "=r"(r[2]), "=r"(r[3]) : "r"(addr));
}
__device__ __forceinline__ void mma_f16(float* d, const uint32_t* a, const uint32_t* b) {
    asm volatile(
        "mma.sync.aligned.m16n8k16.row.col.f32.f16.f16.f32 "
        "{%0,%1,%2,%3}, {%4,%5,%6,%7}, {%8,%9}, {%0,%1,%2,%3};"
        : "+f"(d[0]), "+f"(d[1]), "+f"(d[2]), "+f"(d[3])
        : "r"(a[0]), "r"(a[1]), "r"(a[2]), "r"(a[3]), "r"(b[0]), "r"(b[1]));
}
// pack two floats into fp16x2 hi + fp16x2 lo (residual)
__device__ __forceinline__ void pack_hilo(float a, float b, uint32_t& h, uint32_t& l) {
    __half2 hv = __floats2half2_rn(a, b);
    float2 hf = __half22float2(hv);
    __half2 lv = __floats2half2_rn(a - hf.x, b - hf.y);
    h = *(uint32_t*)&hv;
    l = *(uint32_t*)&lv;
}

// ---------------------------------------------------------------------------
// fp32 -> fp16 hi/lo split (same layout)
// ---------------------------------------------------------------------------
__global__ __launch_bounds__(256) void cvt_hilo(
    const float* __restrict__ in, __half* __restrict__ hi,
    __half* __restrict__ lo, int n)
{
    int i = (blockIdx.x * 256 + threadIdx.x) * 4;
    if (i >= n) return;
    float4 v = *(const float4*)(in + i);
    float f[4] = {v.x, v.y, v.z, v.w};
    __align__(8) __half hb[4];
    __align__(8) __half lb[4];
#pragma unroll
    for (int j = 0; j < 4; j++) {
        hb[j] = __float2half_rn(f[j]);
        lb[j] = __float2half_rn(f[j] - __half2float(hb[j]));
    }
    *(uint2*)(hi + i) = *(uint2*)hb;
    *(uint2*)(lo + i) = *(uint2*)lb;
}

// ---------------------------------------------------------------------------
// W [K,N] fp32 row-major -> W^T hi/lo fp16 [N,K]
// ---------------------------------------------------------------------------
__global__ __launch_bounds__(256) void cvt_w_t(
    const float* __restrict__ W, __half* __restrict__ Thi,
    __half* __restrict__ Tlo, int K, int N)
{
    __shared__ float tile[32][33];
    const int n0 = blockIdx.x * 32, k0 = blockIdx.y * 32;
    const int tx = threadIdx.x & 31, ty = threadIdx.x >> 5;   // 32 x 8
#pragma unroll
    for (int r = 0; r < 4; r++)
        tile[ty + 8 * r][tx] = W[(size_t)(k0 + ty + 8 * r) * N + n0 + tx];
    __syncthreads();
#pragma unroll
    for (int r = 0; r < 4; r++) {
        int n = n0 + ty + 8 * r;
        float v = tile[tx][ty + 8 * r];
        __half h = __float2half_rn(v);
        __half l = __float2half_rn(v - __half2float(h));
        Thi[(size_t)n * K + k0 + tx] = h;
        Tlo[(size_t)n * K + k0 + tx] = l;
    }
}

// ---------------------------------------------------------------------------
// mma.sync fp16 split GEMM: C[M,N] = A[M,K] @ B^T  (A [M,K] hi/lo, B [N,K])
// NP=3: Ahi*Bhi + Alo*Bhi + Ahi*Blo  (needs Blo)
// NP=2: Ahi*Bhi + Alo*Bhi            (B quantized to fp16; no Blo tile at all)
// CTA: 128x256 tile, BK=64, 256 threads (8 warps, 2Mx4N, warp tile 64x64),
// cp.async double-buffered, ONE __syncthreads per k-chunk.
// MODE 0: fp32 out; MODE 1: hi/lo fp16 out.
// ---------------------------------------------------------------------------
#define BK_G   64
#define LDT    72                        // 64 + 8 pad (fp16 elems) -> 144B rows
#define MAT_A  (128 * LDT * 2)           // 18432 B (A hi or lo, 128 rows)
#define MAT_Bb (256 * LDT * 2)           // 36864 B (B hi or lo, 256 rows)
#define SMEM_G3 (2 * (2 * MAT_A + 2 * MAT_Bb))   // 221184 B
#define SMEM_G2 (2 * (2 * MAT_A + 1 * MAT_Bb))   // 147456 B

template<int MODE, int NP>
__global__ __launch_bounds__(256, 1)
void gemm_mma_f16(const __half* __restrict__ Ahi,
                  const __half* __restrict__ Alo,
                  const __half* __restrict__ Bhi,
                  const __half* __restrict__ Blo,
                  float* __restrict__ Cf,
                  __half* __restrict__ Chi,
                  __half* __restrict__ Clo,
                  int N, int K)
{
    constexpr int BUF_B = 2 * MAT_A + (NP == 3 ? 2 : 1) * MAT_Bb;

    extern __shared__ __align__(128) char smem[];
    const int t    = threadIdx.x;
    const int lane = t & 31;
    const int wid  = t >> 5;
    const int bn   = blockIdx.x * 256;
    const int bm   = blockIdx.y * 128;
    const int wm   = (wid & 1) * 64;      // 2 warps in M
    const int wn   = (wid >> 1) * 64;     // 4 warps in N

    float acc[4][8][4];
#pragma unroll
    for (int i = 0; i < 4; i++)
#pragma unroll
        for (int j = 0; j < 8; j++)
#pragma unroll
            for (int r = 0; r < 4; r++) acc[i][j][r] = 0.f;

    const int nk = K / BK_G;   // 16

    auto load_tile = [&](int c, int buf) {
        char* bp = smem + buf * BUF_B;
        const int kc = c * BK_G;
        // A hi/lo: 128 rows x 8 chunks of 16B
#pragma unroll
        for (int i = 0; i < 4; i++) {
            int idx = t + 256 * i;
            int row = idx >> 3;            // 0..127
            int c16 = idx & 7;
            uint32_t so = (uint32_t)(row * LDT + c16 * 8) * 2;
            size_t ga = (size_t)(bm + row) * K + kc + c16 * 8;
            cp16(bp + so,         Ahi + ga);
            cp16(bp + MAT_A + so, Alo + ga);
        }
        // B: 256 rows x 8 chunks of 16B (hi always, lo only for NP=3)
#pragma unroll
        for (int i = 0; i < 8; i++) {
            int idx = t + 256 * i;
            int row = idx >> 3;            // 0..255
            int c16 = idx & 7;
            uint32_t so = (uint32_t)(row * LDT + c16 * 8) * 2;
            size_t gb = (size_t)(bn + row) * K + kc + c16 * 8;
            cp16(bp + 2 * MAT_A + so, Bhi + gb);
            if (NP == 3)
                cp16(bp + 2 * MAT_A + MAT_Bb + so, Blo + gb);
        }
    };

    load_tile(0, 0);
    asm volatile("cp.async.commit_group;" ::: "memory");

    for (int c = 0; c < nk; c++) {
        asm volatile("cp.async.wait_group 0;" ::: "memory");
        __syncthreads();                   // loads(c) visible; compute(c-1) drained
        if (c + 1 < nk) {
            load_tile(c + 1, (c + 1) & 1);
            asm volatile("cp.async.commit_group;" ::: "memory");
        }

        const char* bp = smem + (c & 1) * BUF_B;
        const __half* sAhi = (const __half*)(bp);
        const __half* sAlo = (const __half*)(bp + MAT_A);
        const __half* sBhi = (const __half*)(bp + 2 * MAT_A);
        const __half* sBlo = (const __half*)(bp + 2 * MAT_A + MAT_Bb);

#pragma unroll
        for (int ks = 0; ks < BK_G; ks += 16) {
            uint32_t ah[4][4], al[4][4], bh[4][4], bl[4][4];
            const int arow = lane & 15;
            const int acol = ks + (lane >> 4) * 8;
#pragma unroll
            for (int mf = 0; mf < 4; mf++) {
                uint32_t off = (uint32_t)((wm + mf * 16 + arow) * LDT + acol);
                ldx4(ah[mf], smem_u32(sAhi + off));
                ldx4(al[mf], smem_u32(sAlo + off));
            }
            const int g    = lane >> 3;
            const int brow = ((g >> 1) << 3) + (lane & 7);
            const int bcol = ks + (g & 1) * 8;
#pragma unroll
            for (int nf2 = 0; nf2 < 4; nf2++) {
                uint32_t off = (uint32_t)((wn + nf2 * 16 + brow) * LDT + bcol);
                ldx4(bh[nf2], smem_u32(sBhi + off));
                if (NP == 3) ldx4(bl[nf2], smem_u32(sBlo + off));
            }
#pragma unroll
            for (int p = 0; p < NP; p++)
#pragma unroll
                for (int mf = 0; mf < 4; mf++)
#pragma unroll
                    for (int nf2 = 0; nf2 < 4; nf2++)
#pragma unroll
                        for (int j = 0; j < 2; j++) {
                            const uint32_t* av = (p == 1) ? al[mf] : ah[mf];
                            const uint32_t* bv = (p == 2) ? &bl[nf2][j * 2]
                                                          : &bh[nf2][j * 2];
                            mma_f16(acc[mf][nf2 * 2 + j], av, bv);
                        }
        }
    }

#pragma unroll
    for (int mf = 0; mf < 4; mf++)
#pragma unroll
        for (int nf = 0; nf < 8; nf++) {
            int row = bm + wm + mf * 16 + (lane >> 2);
            int col = bn + wn + nf * 8 + (lane & 3) * 2;
            if (MODE == 0) {
                *(float2*)&Cf[(size_t)row * N + col] =
                    make_float2(acc[mf][nf][0], acc[mf][nf][1]);
                *(float2*)&Cf[(size_t)(row + 8) * N + col] =
                    make_float2(acc[mf][nf][2], acc[mf][nf][3]);
            } else {
                uint32_t h, l;
                pack_hilo(acc[mf][nf][0], acc[mf][nf][1], h, l);
                *(uint32_t*)&Chi[(size_t)row * N + col] = h;
                *(uint32_t*)&Clo[(size_t)row * N + col] = l;
                pack_hilo(acc[mf][nf][2], acc[mf][nf][3], h, l);
                *(uint32_t*)&Chi[(size_t)(row + 8) * N + col] = h;
                *(uint32_t*)&Clo[(size_t)(row + 8) * N + col] = l;
            }
        }
}

// ---------------------------------------------------------------------------
// Tensor-core flash attention, fp16 2-product:
//   S = (Qhi+Qlo) K_hi^T   (K quantized to fp16)
//   O = (Phi+Plo) V_hi     (V quantized to fp16)
// CTA 128 threads (4 warps), 64-q tile, 64-k blocks, 2048 CTAs.
// smem: Qh Ql Kh Vh (lo tiles for K/V eliminated).
// ---------------------------------------------------------------------------
#define LDA_A 72
#define TILE_E (64 * LDA_A)                 // elems per smem matrix
#define ATTN_SMEM (4 * TILE_E * 2)          // Qh Ql Kh Vh = 36864 B

__global__ __launch_bounds__(128) void attn_mma(
    const __half* __restrict__ Shi, const __half* __restrict__ Slo,
    __half* __restrict__ Yhi, __half* __restrict__ Ylo)
{
    extern __shared__ __align__(16) char smraw[];
    __half* Qh = (__half*)smraw;
    __half* Ql = Qh + TILE_E;
    __half* Kh = Ql + TILE_E;
    __half* Vh = Kh + TILE_E;

    const int it = blockIdx.x;          // q-tile (0..31)
    const int h  = blockIdx.y;
    const int b  = blockIdx.z;
    const int t  = threadIdx.x;
    const int lane = t & 31;
    const int wid  = t >> 5;
    const int wq   = wid * 16;          // warp's q-row offset in tile

    const int q0   = it * 64;
    const size_t tok0 = (size_t)b * L_;
    const int qcol = h * D_;
    const int kcol = C_ + h * D_;
    const int vcol = 2 * C_ + h * D_;

    // ---- stage Q tile (hi/lo), 64 rows x 128B each ----
#pragma unroll
    for (int i = 0; i < 4; i++) {
        int idx = t + 128 * i;
        int row = idx >> 3;
        int ch  = (idx & 7) * 8;
        size_t g = (tok0 + q0 + row) * (3 * C_) + qcol + ch;
        cp16(Qh + row * LDA_A + ch, Shi + g);
        cp16(Ql + row * LDA_A + ch, Slo + g);
    }
    asm volatile("cp.async.commit_group;" ::: "memory");
    asm volatile("cp.async.wait_group 0;" ::: "memory");
    __syncthreads();

    // ---- Q fragments (A-frags, m16k16 x 4 kgroups, hi+lo) ----
    uint32_t qh[4][4], ql[4][4];
    {
        const int arow = lane & 15;
        const int acol = (lane >> 4) * 8;
#pragma unroll
        for (int kg = 0; kg < 4; kg++) {
            uint32_t off = (uint32_t)((wq + arow) * LDA_A + kg * 16 + acol);
            ldx4(qh[kg], smem_u32(Qh + off));
            ldx4(ql[kg], smem_u32(Ql + off));
        }
    }

    const int r0 = lane >> 2;           // row pair within m16
    float m[2] = {-1e30f, -1e30f};
    float lsum[2] = {0.f, 0.f};
    float O[8][4];
#pragma unroll
    for (int f = 0; f < 8; f++)
#pragma unroll
        for (int e = 0; e < 4; e++) O[f][e] = 0.f;

    for (int jb = 0; jb <= it; jb++) {
        const int k0 = jb * 64;
        __syncthreads();   // all warps done with previous K/V tiles

        // ---- stage K/V hi tiles ----
#pragma unroll
        for (int i = 0; i < 4; i++) {
            int idx = t + 128 * i;
            int row = idx >> 3;
            int ch  = (idx & 7) * 8;
            size_t gk = (tok0 + k0 + row) * (3 * C_) + kcol + ch;
            size_t gv = (tok0 + k0 + row) * (3 * C_) + vcol + ch;
            uint32_t so = row * LDA_A + ch;
            cp16(Kh + so, Shi + gk);
            cp16(Vh + so, Shi + gv);
        }
        asm volatile("cp.async.commit_group;" ::: "memory");
        asm volatile("cp.async.wait_group 0;" ::: "memory");
        __syncthreads();

        // ---- S = (Qhi+Qlo) Kh^T (scores frags: 8 x n8) ----
        float s[8][4];
#pragma unroll
        for (int f = 0; f < 8; f++)
#pragma unroll
            for (int e = 0; e < 4; e++) s[f][e] = 0.f;

        {
            const int g    = lane >> 3;
            const int brow = ((g >> 1) << 3) + (lane & 7);
            const int bcol = (g & 1) * 8;
#pragma unroll
            for (int kg = 0; kg < 4; kg++) {
#pragma unroll
                for (int nf2 = 0; nf2 < 4; nf2++) {
                    uint32_t kh[4];
                    uint32_t off = (uint32_t)((nf2 * 16 + brow) * LDA_A + kg * 16 + bcol);
                    ldx4(kh, smem_u32(Kh + off));
#pragma unroll
                    for (int j = 0; j < 2; j++) {
                        float* d = s[nf2 * 2 + j];
                        mma_f16(d, qh[kg], &kh[j * 2]);
                        mma_f16(d, ql[kg], &kh[j * 2]);
                    }
                }
            }
        }

        // ---- scale + causal mask ----
        const bool diag = (jb == it);
#pragma unroll
        for (int f = 0; f < 8; f++) {
#pragma unroll
            for (int e = 0; e < 4; e++) {
                int qi = q0 + wq + r0 + (e >> 1) * 8;
                int ki = k0 + f * 8 + (lane & 3) * 2 + (e & 1);
                float v = s[f][e] * 0.125f;
                s[f][e] = (diag && ki > qi) ? -1e30f : v;
            }
        }

        // ---- online softmax (rows r0, r0+8) ----
#pragma unroll
        for (int r = 0; r < 2; r++) {
            float vmax = -1e30f;
#pragma unroll
            for (int f = 0; f < 8; f++)
                vmax = fmaxf(vmax, fmaxf(s[f][2 * r], s[f][2 * r + 1]));
            vmax = fmaxf(vmax, __shfl_xor_sync(0xffffffffu, vmax, 1));
            vmax = fmaxf(vmax, __shfl_xor_sync(0xffffffffu, vmax, 2));
            float nm = fmaxf(m[r], vmax);
            float alpha = __expf(m[r] - nm);
            m[r] = nm;
            float rs = 0.f;
#pragma unroll
            for (int f = 0; f < 8; f++) {
                float p0 = __expf(s[f][2 * r] - nm);
                float p1 = __expf(s[f][2 * r + 1] - nm);
                s[f][2 * r] = p0; s[f][2 * r + 1] = p1;
                rs += p0 + p1;
            }
            rs += __shfl_xor_sync(0xffffffffu, rs, 1);
            rs += __shfl_xor_sync(0xffffffffu, rs, 2);
            lsum[r] = lsum[r] * alpha + rs;
#pragma unroll
            for (int f = 0; f < 8; f++) {
                O[f][2 * r] *= alpha;
                O[f][2 * r + 1] *= alpha;
            }
        }

        // ---- O += (Phi+Plo) Vh (V via ldmatrix.trans) ----
        {
            const int g = lane >> 3;
            const int vrow = (g & 1) * 8 + (lane & 7);
            const int vcolb = (g >> 1) * 8;
#pragma unroll
            for (int kg = 0; kg < 4; kg++) {
                uint32_t pa_h[4], pa_l[4];
                pack_hilo(s[2 * kg][0],     s[2 * kg][1],     pa_h[0], pa_l[0]);
                pack_hilo(s[2 * kg][2],     s[2 * kg][3],     pa_h[1], pa_l[1]);
                pack_hilo(s[2 * kg + 1][0], s[2 * kg + 1][1], pa_h[2], pa_l[2]);
                pack_hilo(s[2 * kg + 1][2], s[2 * kg + 1][3], pa_h[3], pa_l[3]);
#pragma unroll
                for (int nf2 = 0; nf2 < 4; nf2++) {
                    uint32_t vh[4];
                    uint32_t off = (uint32_t)((kg * 16 + vrow) * LDA_A + nf2 * 16 + vcolb);
                    ldx4t(vh, smem_u32(Vh + off));
#pragma unroll
                    for (int j = 0; j < 2; j++) {
                        float* d = O[nf2 * 2 + j];
                        mma_f16(d, pa_h, &vh[j * 2]);
                        mma_f16(d, pa_l, &vh[j * 2]);
                    }
                }
            }
        }
    }

    // ---- normalize + write hi/lo fp16 output [token, C] ----
    const float inv0 = 1.0f / lsum[0];
    const float inv1 = 1.0f / lsum[1];
#pragma unroll
    for (int f = 0; f < 8; f++) {
        int col = h * D_ + f * 8 + (lane & 3) * 2;
        size_t row0 = (tok0 + q0 + wq + r0) * C_ + col;
        size_t row1 = (tok0 + q0 + wq + r0 + 8) * C_ + col;
        uint32_t hh, ll;
        pack_hilo(O[f][0] * inv0, O[f][1] * inv0, hh, ll);
        *(uint32_t*)&Yhi[row0] = hh;
        *(uint32_t*)&Ylo[row0] = ll;
        pack_hilo(O[f][2] * inv1, O[f][3] * inv1, hh, ll);
        *(uint32_t*)&Yhi[row1] = hh;
        *(uint32_t*)&Ylo[row1] = ll;
    }
}

// ---------------------------------------------------------------------------

extern "C" void kernel_launch(void* const* d_in, const int* in_sizes, int n_in,
                              void* d_out, int out_size)
{
    const float* x      = (const float*)d_in[0];   // [4,2048,1024]
    const float* w_attn = (const float*)d_in[1];   // [1024,3072]
    const float* w_proj = (const float*)d_in[2];   // [1024,1024]
    float* out = (float*)d_out;                    // [4,2048,1024]

    __half *ahi, *alo, *bhi, *blo, *shi, *slo;
    cudaGetSymbolAddress((void**)&ahi, g_Ahi);
    cudaGetSymbolAddress((void**)&alo, g_Alo);
    cudaGetSymbolAddress((void**)&bhi, g_Bhi);
    cudaGetSymbolAddress((void**)&blo, g_Blo);
    cudaGetSymbolAddress((void**)&shi, g_Shi);
    cudaGetSymbolAddress((void**)&slo, g_Slo);

    cudaFuncSetAttribute(gemm_mma_f16<1, 3>,
                         cudaFuncAttributeMaxDynamicSharedMemorySize, SMEM_G3);
    cudaFuncSetAttribute(gemm_mma_f16<0, 2>,
                         cudaFuncAttributeMaxDynamicSharedMemorySize, SMEM_G2);
    cudaFuncSetAttribute(attn_mma,
                         cudaFuncAttributeMaxDynamicSharedMemorySize, ATTN_SMEM);

    const int nA = MTOK * C_;

    // 1) split x -> fp16 hi/lo ; transpose+split w_attn -> [3C, C]
    cvt_hilo<<<nA / 4 / 256, 256>>>(x, ahi, alo, nA);
    cvt_w_t<<<dim3(3 * C_ / 32, C_ / 32), 256>>>(w_attn, bhi, blo, C_, 3 * C_);

    // 2) QKV GEMM (fp16 x3 products) -> hi/lo fp16 QKV
    gemm_mma_f16<1, 3><<<dim3(3 * C_ / 256, MTOK / 128), 256, SMEM_G3>>>(
        ahi, alo, bhi, blo, nullptr, shi, slo, 3 * C_, C_);

    // 3) tensor-core causal flash attention (2-product) -> hi/lo into proj bufs
    attn_mma<<<dim3(L_ / 64, H_, B_), 128, ATTN_SMEM>>>(shi, slo, ahi, alo);

    // 4) transpose+split w_proj
    cvt_w_t<<<dim3(C_ / 32, C_ / 32), 256>>>(w_proj, bhi, blo, C_, C_);

    // 5) proj GEMM (2-product, no Blo tile) -> fp32 out
    gemm_mma_f16<0, 2><<<dim3(C_ / 256, MTOK / 128), 256, SMEM_G2>>>(
        ahi, alo, bhi, blo, out, nullptr, nullptr, C_, C_);
}

// round 15
// speedup vs baseline: 1.5823x; 1.1840x over previous
#include <cuda_runtime.h>
#include <cuda_fp16.h>
#include <cstdint>

#define B_ 4
#define L_ 2048
#define C_ 1024
#define H_ 16
#define D_ 64
#define MTOK (B_ * L_)   // 8192 token rows

// ---------------------------------------------------------------------------
// Scratch (allocation-free rule: __device__ globals)
// ---------------------------------------------------------------------------
__device__ __half g_Ahi[(size_t)MTOK * C_];     // activation hi  [M,K]
__device__ __half g_Alo[(size_t)MTOK * C_];     // activation lo  [M,K]
__device__ __half g_Bhi[(size_t)3 * C_ * C_];   // weight^T hi    [N,K]
__device__ __half g_Blo[(size_t)3 * C_ * C_];   // weight^T lo    [N,K]
__device__ __half g_Shi[(size_t)MTOK * 3 * C_]; // QKV hi [8192,3072]
__device__ __half g_Slo[(size_t)MTOK * 3 * C_]; // QKV lo

// ---------------------------------------------------------------------------
// helpers
// ---------------------------------------------------------------------------
__device__ __forceinline__ uint32_t smem_u32(const void* p) {
    return (uint32_t)__cvta_generic_to_shared(p);
}
__device__ __forceinline__ void cp16(void* s, const void* g) {
    uint32_t sa = smem_u32(s);
    asm volatile("cp.async.cg.shared.global [%0], [%1], 16;" :: "r"(sa), "l"(g) : "memory");
}
__device__ __forceinline__ void ldx4(uint32_t* r, uint32_t addr) {
    asm volatile("ldmatrix.sync.aligned.m8n8.x4.shared.b16 {%0,%1,%2,%3}, [%4];"
                 : "=r"(r[0]), "=r"(r[1]), "=r"(r[2]), "=r"(r[3]) : "r"(addr));
}
__device__ __forceinline__ void ldx4t(uint32_t* r, uint32_t addr) {
    asm volatile("ldmatrix.sync.aligned.m8n8.x4.trans.shared.b16 {%0,%1,%2,%3}, [%4];"
                 : "=r"(r[0]), "=r"(r[1]), "=r"(r[2]), "=r"(r[3]) : "r"(addr));
}
__device__ __forceinline__ void mma_f16(float* d, const uint32_t* a, const uint32_t* b) {
    asm volatile(
        "mma.sync.aligned.m16n8k16.row.col.f32.f16.f16.f32 "
        "{%0,%1,%2,%3}, {%4,%5,%6,%7}, {%8,%9}, {%0,%1,%2,%3};"
        : "+f"(d[0]), "+f"(d[1]), "+f"(d[2]), "+f"(d[3])
        : "r"(a[0]), "r"(a[1]), "r"(a[2]), "r"(a[3]), "r"(b[0]), "r"(b[1]));
}
// pack two floats into fp16x2 hi + fp16x2 lo (residual)
__device__ __forceinline__ void pack_hilo(float a, float b, uint32_t& h, uint32_t& l) {
    __half2 hv = __floats2half2_rn(a, b);
    float2 hf = __half22float2(hv);
    __half2 lv = __floats2half2_rn(a - hf.x, b - hf.y);
    h = *(uint32_t*)&hv;
    l = *(uint32_t*)&lv;
}

// ---------------------------------------------------------------------------
// fp32 -> fp16 hi/lo split (same layout)
// ---------------------------------------------------------------------------
__global__ __launch_bounds__(256) void cvt_hilo(
    const float* __restrict__ in, __half* __restrict__ hi,
    __half* __restrict__ lo, int n)
{
    int i = (blockIdx.x * 256 + threadIdx.x) * 4;
    if (i >= n) return;
    float4 v = *(const float4*)(in + i);
    float f[4] = {v.x, v.y, v.z, v.w};
    __align__(8) __half hb[4];
    __align__(8) __half lb[4];
#pragma unroll
    for (int j = 0; j < 4; j++) {
        hb[j] = __float2half_rn(f[j]);
        lb[j] = __float2half_rn(f[j] - __half2float(hb[j]));
    }
    *(uint2*)(hi + i) = *(uint2*)hb;
    *(uint2*)(lo + i) = *(uint2*)lb;
}

// ---------------------------------------------------------------------------
// W [K,N] fp32 row-major -> W^T hi/lo fp16 [N,K]
// ---------------------------------------------------------------------------
__global__ __launch_bounds__(256) void cvt_w_t(
    const float* __restrict__ W, __half* __restrict__ Thi,
    __half* __restrict__ Tlo, int K, int N)
{
    __shared__ float tile[32][33];
    const int n0 = blockIdx.x * 32, k0 = blockIdx.y * 32;
    const int tx = threadIdx.x & 31, ty = threadIdx.x >> 5;   // 32 x 8
#pragma unroll
    for (int r = 0; r < 4; r++)
        tile[ty + 8 * r][tx] = W[(size_t)(k0 + ty + 8 * r) * N + n0 + tx];
    __syncthreads();
#pragma unroll
    for (int r = 0; r < 4; r++) {
        int n = n0 + ty + 8 * r;
        float v = tile[tx][ty + 8 * r];
        __half h = __float2half_rn(v);
        __half l = __float2half_rn(v - __half2float(h));
        Thi[(size_t)n * K + k0 + tx] = h;
        Tlo[(size_t)n * K + k0 + tx] = l;
    }
}

// ---------------------------------------------------------------------------
// mma.sync fp16 split GEMM: C[M,N] = A[M,K] @ B^T  (A [M,K] hi/lo, B [N,K])
// NP=3: Ahi*Bhi + Alo*Bhi + Ahi*Blo  (needs Blo)
// NP=2: Ahi*Bhi + Alo*Bhi            (B quantized to fp16; no Blo tile at all)
// CTA: 128x256 tile, BK=64, 256 threads (8 warps, 2Mx4N, warp tile 64x64),
// cp.async double-buffered, ONE __syncthreads per k-chunk.
// MODE 0: fp32 out; MODE 1: hi/lo fp16 out.
// ---------------------------------------------------------------------------
#define BK_G   64
#define LDT    72                        // 64 + 8 pad (fp16 elems) -> 144B rows
#define MAT_A  (128 * LDT * 2)           // 18432 B (A hi or lo, 128 rows)
#define MAT_Bb (256 * LDT * 2)           // 36864 B (B hi or lo, 256 rows)
#define SMEM_G3 (2 * (2 * MAT_A + 2 * MAT_Bb))   // 221184 B
#define SMEM_G2 (2 * (2 * MAT_A + 1 * MAT_Bb))   // 147456 B

template<int MODE, int NP>
__global__ __launch_bounds__(256, 1)
void gemm_mma_f16(const __half* __restrict__ Ahi,
                  const __half* __restrict__ Alo,
                  const __half* __restrict__ Bhi,
                  const __half* __restrict__ Blo,
                  float* __restrict__ Cf,
                  __half* __restrict__ Chi,
                  __half* __restrict__ Clo,
                  int N, int K)
{
    constexpr int BUF_B = 2 * MAT_A + (NP == 3 ? 2 : 1) * MAT_Bb;

    extern __shared__ __align__(128) char smem[];
    const int t    = threadIdx.x;
    const int lane = t & 31;
    const int wid  = t >> 5;
    const int bn   = blockIdx.x * 256;
    const int bm   = blockIdx.y * 128;
    const int wm   = (wid & 1) * 64;      // 2 warps in M
    const int wn   = (wid >> 1) * 64;     // 4 warps in N

    float acc[4][8][4];
#pragma unroll
    for (int i = 0; i < 4; i++)
#pragma unroll
        for (int j = 0; j < 8; j++)
#pragma unroll
            for (int r = 0; r < 4; r++) acc[i][j][r] = 0.f;

    const int nk = K / BK_G;   // 16

    auto load_tile = [&](int c, int buf) {
        char* bp = smem + buf * BUF_B;
        const int kc = c * BK_G;
        // A hi/lo: 128 rows x 8 chunks of 16B
#pragma unroll
        for (int i = 0; i < 4; i++) {
            int idx = t + 256 * i;
            int row = idx >> 3;            // 0..127
            int c16 = idx & 7;
            uint32_t so = (uint32_t)(row * LDT + c16 * 8) * 2;
            size_t ga = (size_t)(bm + row) * K + kc + c16 * 8;
            cp16(bp + so,         Ahi + ga);
            cp16(bp + MAT_A + so, Alo + ga);
        }
        // B: 256 rows x 8 chunks of 16B (hi always, lo only for NP=3)
#pragma unroll
        for (int i = 0; i < 8; i++) {
            int idx = t + 256 * i;
            int row = idx >> 3;            // 0..255
            int c16 = idx & 7;
            uint32_t so = (uint32_t)(row * LDT + c16 * 8) * 2;
            size_t gb = (size_t)(bn + row) * K + kc + c16 * 8;
            cp16(bp + 2 * MAT_A + so, Bhi + gb);
            if (NP == 3)
                cp16(bp + 2 * MAT_A + MAT_Bb + so, Blo + gb);
        }
    };

    load_tile(0, 0);
    asm volatile("cp.async.commit_group;" ::: "memory");

    for (int c = 0; c < nk; c++) {
        asm volatile("cp.async.wait_group 0;" ::: "memory");
        __syncthreads();                   // loads(c) visible; compute(c-1) drained
        if (c + 1 < nk) {
            load_tile(c + 1, (c + 1) & 1);
            asm volatile("cp.async.commit_group;" ::: "memory");
        }

        const char* bp = smem + (c & 1) * BUF_B;
        const __half* sAhi = (const __half*)(bp);
        const __half* sAlo = (const __half*)(bp + MAT_A);
        const __half* sBhi = (const __half*)(bp + 2 * MAT_A);
        const __half* sBlo = (const __half*)(bp + 2 * MAT_A + MAT_Bb);

#pragma unroll
        for (int ks = 0; ks < BK_G; ks += 16) {
            uint32_t ah[4][4], al[4][4], bh[4][4], bl[4][4];
            const int arow = lane & 15;
            const int acol = ks + (lane >> 4) * 8;
#pragma unroll
            for (int mf = 0; mf < 4; mf++) {
                uint32_t off = (uint32_t)((wm + mf * 16 + arow) * LDT + acol);
                ldx4(ah[mf], smem_u32(sAhi + off));
                ldx4(al[mf], smem_u32(sAlo + off));
            }
            const int g    = lane >> 3;
            const int brow = ((g >> 1) << 3) + (lane & 7);
            const int bcol = ks + (g & 1) * 8;
#pragma unroll
            for (int nf2 = 0; nf2 < 4; nf2++) {
                uint32_t off = (uint32_t)((wn + nf2 * 16 + brow) * LDT + bcol);
                ldx4(bh[nf2], smem_u32(sBhi + off));
                if (NP == 3) ldx4(bl[nf2], smem_u32(sBlo + off));
            }
#pragma unroll
            for (int p = 0; p < NP; p++)
#pragma unroll
                for (int mf = 0; mf < 4; mf++)
#pragma unroll
                    for (int nf2 = 0; nf2 < 4; nf2++)
#pragma unroll
                        for (int j = 0; j < 2; j++) {
                            const uint32_t* av = (p == 1) ? al[mf] : ah[mf];
                            const uint32_t* bv = (p == 2) ? &bl[nf2][j * 2]
                                                          : &bh[nf2][j * 2];
                            mma_f16(acc[mf][nf2 * 2 + j], av, bv);
                        }
        }
    }

#pragma unroll
    for (int mf = 0; mf < 4; mf++)
#pragma unroll
        for (int nf = 0; nf < 8; nf++) {
            int row = bm + wm + mf * 16 + (lane >> 2);
            int col = bn + wn + nf * 8 + (lane & 3) * 2;
            if (MODE == 0) {
                *(float2*)&Cf[(size_t)row * N + col] =
                    make_float2(acc[mf][nf][0], acc[mf][nf][1]);
                *(float2*)&Cf[(size_t)(row + 8) * N + col] =
                    make_float2(acc[mf][nf][2], acc[mf][nf][3]);
            } else {
                uint32_t h, l;
                pack_hilo(acc[mf][nf][0], acc[mf][nf][1], h, l);
                *(uint32_t*)&Chi[(size_t)row * N + col] = h;
                *(uint32_t*)&Clo[(size_t)row * N + col] = l;
                pack_hilo(acc[mf][nf][2], acc[mf][nf][3], h, l);
                *(uint32_t*)&Chi[(size_t)(row + 8) * N + col] = h;
                *(uint32_t*)&Clo[(size_t)(row + 8) * N + col] = l;
            }
        }
}

// ---------------------------------------------------------------------------
// Tensor-core flash attention, fp16 2-product:
//   S = (Qhi+Qlo) K_hi^T   (K quantized to fp16)
//   O = (Phi+Plo) V_hi     (V quantized to fp16)
// CTA 128 threads (4 warps), 64-q tile, 64-k blocks, 2048 CTAs.
// smem: Qh Ql Kh Vh (lo tiles for K/V eliminated).
// ---------------------------------------------------------------------------
#define LDA_A 72
#define TILE_E (64 * LDA_A)                 // elems per smem matrix
#define ATTN_SMEM (4 * TILE_E * 2)          // Qh Ql Kh Vh = 36864 B

__global__ __launch_bounds__(128) void attn_mma(
    const __half* __restrict__ Shi, const __half* __restrict__ Slo,
    __half* __restrict__ Yhi, __half* __restrict__ Ylo)
{
    extern __shared__ __align__(16) char smraw[];
    __half* Qh = (__half*)smraw;
    __half* Ql = Qh + TILE_E;
    __half* Kh = Ql + TILE_E;
    __half* Vh = Kh + TILE_E;

    const int it = blockIdx.x;          // q-tile (0..31)
    const int h  = blockIdx.y;
    const int b  = blockIdx.z;
    const int t  = threadIdx.x;
    const int lane = t & 31;
    const int wid  = t >> 5;
    const int wq   = wid * 16;          // warp's q-row offset in tile

    const int q0   = it * 64;
    const size_t tok0 = (size_t)b * L_;
    const int qcol = h * D_;
    const int kcol = C_ + h * D_;
    const int vcol = 2 * C_ + h * D_;

    // ---- stage Q tile (hi/lo), 64 rows x 128B each ----
#pragma unroll
    for (int i = 0; i < 4; i++) {
        int idx = t + 128 * i;
        int row = idx >> 3;
        int ch  = (idx & 7) * 8;
        size_t g = (tok0 + q0 + row) * (3 * C_) + qcol + ch;
        cp16(Qh + row * LDA_A + ch, Shi + g);
        cp16(Ql + row * LDA_A + ch, Slo + g);
    }
    asm volatile("cp.async.commit_group;" ::: "memory");
    asm volatile("cp.async.wait_group 0;" ::: "memory");
    __syncthreads();

    // ---- Q fragments (A-frags, m16k16 x 4 kgroups, hi+lo) ----
    uint32_t qh[4][4], ql[4][4];
    {
        const int arow = lane & 15;
        const int acol = (lane >> 4) * 8;
#pragma unroll
        for (int kg = 0; kg < 4; kg++) {
            uint32_t off = (uint32_t)((wq + arow) * LDA_A + kg * 16 + acol);
            ldx4(qh[kg], smem_u32(Qh + off));
            ldx4(ql[kg], smem_u32(Ql + off));
        }
    }

    const int r0 = lane >> 2;           // row pair within m16
    float m[2] = {-1e30f, -1e30f};
    float lsum[2] = {0.f, 0.f};
    float O[8][4];
#pragma unroll
    for (int f = 0; f < 8; f++)
#pragma unroll
        for (int e = 0; e < 4; e++) O[f][e] = 0.f;

    for (int jb = 0; jb <= it; jb++) {
        const int k0 = jb * 64;
        __syncthreads();   // all warps done with previous K/V tiles

        // ---- stage K/V hi tiles ----
#pragma unroll
        for (int i = 0; i < 4; i++) {
            int idx = t + 128 * i;
            int row = idx >> 3;
            int ch  = (idx & 7) * 8;
            size_t gk = (tok0 + k0 + row) * (3 * C_) + kcol + ch;
            size_t gv = (tok0 + k0 + row) * (3 * C_) + vcol + ch;
            uint32_t so = row * LDA_A + ch;
            cp16(Kh + so, Shi + gk);
            cp16(Vh + so, Shi + gv);
        }
        asm volatile("cp.async.commit_group;" ::: "memory");
        asm volatile("cp.async.wait_group 0;" ::: "memory");
        __syncthreads();

        // ---- S = (Qhi+Qlo) Kh^T (scores frags: 8 x n8) ----
        float s[8][4];
#pragma unroll
        for (int f = 0; f < 8; f++)
#pragma unroll
            for (int e = 0; e < 4; e++) s[f][e] = 0.f;

        {
            const int g    = lane >> 3;
            const int brow = ((g >> 1) << 3) + (lane & 7);
            const int bcol = (g & 1) * 8;
#pragma unroll
            for (int kg = 0; kg < 4; kg++) {
#pragma unroll
                for (int nf2 = 0; nf2 < 4; nf2++) {
                    uint32_t kh[4];
                    uint32_t off = (uint32_t)((nf2 * 16 + brow) * LDA_A + kg * 16 + bcol);
                    ldx4(kh, smem_u32(Kh + off));
#pragma unroll
                    for (int j = 0; j < 2; j++) {
                        float* d = s[nf2 * 2 + j];
                        mma_f16(d, qh[kg], &kh[j * 2]);
                        mma_f16(d, ql[kg], &kh[j * 2]);
                    }
                }
            }
        }

        // ---- scale + causal mask ----
        const bool diag = (jb == it);
#pragma unroll
        for (int f = 0; f < 8; f++) {
#pragma unroll
            for (int e = 0; e < 4; e++) {
                int qi = q0 + wq + r0 + (e >> 1) * 8;
                int ki = k0 + f * 8 + (lane & 3) * 2 + (e & 1);
                float v = s[f][e] * 0.125f;
                s[f][e] = (diag && ki > qi) ? -1e30f : v;
            }
        }

        // ---- online softmax (rows r0, r0+8) ----
#pragma unroll
        for (int r = 0; r < 2; r++) {
            float vmax = -1e30f;
#pragma unroll
            for (int f = 0; f < 8; f++)
                vmax = fmaxf(vmax, fmaxf(s[f][2 * r], s[f][2 * r + 1]));
            vmax = fmaxf(vmax, __shfl_xor_sync(0xffffffffu, vmax, 1));
            vmax = fmaxf(vmax, __shfl_xor_sync(0xffffffffu, vmax, 2));
            float nm = fmaxf(m[r], vmax);
            float alpha = __expf(m[r] - nm);
            m[r] = nm;
            float rs = 0.f;
#pragma unroll
            for (int f = 0; f < 8; f++) {
                float p0 = __expf(s[f][2 * r] - nm);
                float p1 = __expf(s[f][2 * r + 1] - nm);
                s[f][2 * r] = p0; s[f][2 * r + 1] = p1;
                rs += p0 + p1;
            }
            rs += __shfl_xor_sync(0xffffffffu, rs, 1);
            rs += __shfl_xor_sync(0xffffffffu, rs, 2);
            lsum[r] = lsum[r] * alpha + rs;
#pragma unroll
            for (int f = 0; f < 8; f++) {
                O[f][2 * r] *= alpha;
                O[f][2 * r + 1] *= alpha;
            }
        }

        // ---- O += (Phi+Plo) Vh (V via ldmatrix.trans) ----
        {
            const int g = lane >> 3;
            const int vrow = (g & 1) * 8 + (lane & 7);
            const int vcolb = (g >> 1) * 8;
#pragma unroll
            for (int kg = 0; kg < 4; kg++) {
                uint32_t pa_h[4], pa_l[4];
                pack_hilo(s[2 * kg][0],     s[2 * kg][1],     pa_h[0], pa_l[0]);
                pack_hilo(s[2 * kg][2],     s[2 * kg][3],     pa_h[1], pa_l[1]);
                pack_hilo(s[2 * kg + 1][0], s[2 * kg + 1][1], pa_h[2], pa_l[2]);
                pack_hilo(s[2 * kg + 1][2], s[2 * kg + 1][3], pa_h[3], pa_l[3]);
#pragma unroll
                for (int nf2 = 0; nf2 < 4; nf2++) {
                    uint32_t vh[4];
                    uint32_t off = (uint32_t)((kg * 16 + vrow) * LDA_A + nf2 * 16 + vcolb);
                    ldx4t(vh, smem_u32(Vh + off));
#pragma unroll
                    for (int j = 0; j < 2; j++) {
                        float* d = O[nf2 * 2 + j];
                        mma_f16(d, pa_h, &vh[j * 2]);
                        mma_f16(d, pa_l, &vh[j * 2]);
                    }
                }
            }
        }
    }

    // ---- normalize + write hi/lo fp16 output [token, C] ----
    const float inv0 = 1.0f / lsum[0];
    const float inv1 = 1.0f / lsum[1];
#pragma unroll
    for (int f = 0; f < 8; f++) {
        int col = h * D_ + f * 8 + (lane & 3) * 2;
        size_t row0 = (tok0 + q0 + wq + r0) * C_ + col;
        size_t row1 = (tok0 + q0 + wq + r0 + 8) * C_ + col;
        uint32_t hh, ll;
        pack_hilo(O[f][0] * inv0, O[f][1] * inv0, hh, ll);
        *(uint32_t*)&Yhi[row0] = hh;
        *(uint32_t*)&Ylo[row0] = ll;
        pack_hilo(O[f][2] * inv1, O[f][3] * inv1, hh, ll);
        *(uint32_t*)&Yhi[row1] = hh;
        *(uint32_t*)&Ylo[row1] = ll;
    }
}

// ---------------------------------------------------------------------------

extern "C" void kernel_launch(void* const* d_in, const int* in_sizes, int n_in,
                              void* d_out, int out_size)
{
    const float* x      = (const float*)d_in[0];   // [4,2048,1024]
    const float* w_attn = (const float*)d_in[1];   // [1024,3072]
    const float* w_proj = (const float*)d_in[2];   // [1024,1024]
    float* out = (float*)d_out;                    // [4,2048,1024]

    __half *ahi, *alo, *bhi, *blo, *shi, *slo;
    cudaGetSymbolAddress((void**)&ahi, g_Ahi);
    cudaGetSymbolAddress((void**)&alo, g_Alo);
    cudaGetSymbolAddress((void**)&bhi, g_Bhi);
    cudaGetSymbolAddress((void**)&blo, g_Blo);
    cudaGetSymbolAddress((void**)&shi, g_Shi);
    cudaGetSymbolAddress((void**)&slo, g_Slo);

    cudaFuncSetAttribute(gemm_mma_f16<1, 2>,
                         cudaFuncAttributeMaxDynamicSharedMemorySize, SMEM_G2);
    cudaFuncSetAttribute(gemm_mma_f16<0, 2>,
                         cudaFuncAttributeMaxDynamicSharedMemorySize, SMEM_G2);
    cudaFuncSetAttribute(attn_mma,
                         cudaFuncAttributeMaxDynamicSharedMemorySize, ATTN_SMEM);

    const int nA = MTOK * C_;

    // 1) split x -> fp16 hi/lo ; transpose+split w_attn -> [3C, C]
    cvt_hilo<<<nA / 4 / 256, 256>>>(x, ahi, alo, nA);
    cvt_w_t<<<dim3(3 * C_ / 32, C_ / 32), 256>>>(w_attn, bhi, blo, C_, 3 * C_);

    // 2) QKV GEMM (fp16, 2 products: (Ahi+Alo)·Bhi) -> hi/lo fp16 QKV
    gemm_mma_f16<1, 2><<<dim3(3 * C_ / 256, MTOK / 128), 256, SMEM_G2>>>(
        ahi, alo, bhi, blo, nullptr, shi, slo, 3 * C_, C_);

    // 3) tensor-core causal flash attention (2-product) -> hi/lo into proj bufs
    attn_mma<<<dim3(L_ / 64, H_, B_), 128, ATTN_SMEM>>>(shi, slo, ahi, alo);

    // 4) transpose+split w_proj
    cvt_w_t<<<dim3(C_ / 32, C_ / 32), 256>>>(w_proj, bhi, blo, C_, C_);

    // 5) proj GEMM (2-product, no Blo tile) -> fp32 out
    gemm_mma_f16<0, 2><<<dim3(C_ / 256, MTOK / 128), 256, SMEM_G2>>>(
        ahi, alo, bhi, blo, out, nullptr, nullptr, C_, C_);
}

// round 16
// speedup vs baseline: 1.6055x; 1.0147x over previous
#include <cuda_runtime.h>
#include <cuda_fp16.h>
#include <cstdint>

#define B_ 4
#define L_ 2048
#define C_ 1024
#define H_ 16
#define D_ 64
#define MTOK (B_ * L_)   // 8192 token rows

// ---------------------------------------------------------------------------
// Scratch (allocation-free rule: __device__ globals)
// ---------------------------------------------------------------------------
__device__ __half g_Ahi[(size_t)MTOK * C_];     // activation hi  [M,K]
__device__ __half g_Alo[(size_t)MTOK * C_];     // activation lo  [M,K]
__device__ __half g_Bhi[(size_t)3 * C_ * C_];   // weight^T hi    [N,K]
__device__ __half g_Blo[(size_t)3 * C_ * C_];   // weight^T lo    [N,K]
__device__ __half g_Shi[(size_t)MTOK * 3 * C_]; // QKV hi [8192,3072]
__device__ __half g_Slo[(size_t)MTOK * 3 * C_]; // QKV lo

// ---------------------------------------------------------------------------
// helpers
// ---------------------------------------------------------------------------
__device__ __forceinline__ uint32_t smem_u32(const void* p) {
    return (uint32_t)__cvta_generic_to_shared(p);
}
__device__ __forceinline__ void cp16(void* s, const void* g) {
    uint32_t sa = smem_u32(s);
    asm volatile("cp.async.cg.shared.global [%0], [%1], 16;" :: "r"(sa), "l"(g) : "memory");
}
__device__ __forceinline__ void ldx4(uint32_t* r, uint32_t addr) {
    asm volatile("ldmatrix.sync.aligned.m8n8.x4.shared.b16 {%0,%1,%2,%3}, [%4];"
                 : "=r"(r[0]), "=r"(r[1]), "=r"(r[2]), "=r"(r[3]) : "r"(addr));
}
__device__ __forceinline__ void ldx4t(uint32_t* r, uint32_t addr) {
    asm volatile("ldmatrix.sync.aligned.m8n8.x4.trans.shared.b16 {%0,%1,%2,%3}, [%4];"
                 : "=r"(r[0]), "=r"(r[1]), "=r"(r[2]), "=r"(r[3]) : "r"(addr));
}
__device__ __forceinline__ void mma_f16(float* d, const uint32_t* a, const uint32_t* b) {
    asm volatile(
        "mma.sync.aligned.m16n8k16.row.col.f32.f16.f16.f32 "
        "{%0,%1,%2,%3}, {%4,%5,%6,%7}, {%8,%9}, {%0,%1,%2,%3};"
        : "+f"(d[0]), "+f"(d[1]), "+f"(d[2]), "+f"(d[3])
        : "r"(a[0]), "r"(a[1]), "r"(a[2]), "r"(a[3]), "r"(b[0]), "r"(b[1]));
}
// pack two floats into fp16x2 hi + fp16x2 lo (residual)
__device__ __forceinline__ void pack_hilo(float a, float b, uint32_t& h, uint32_t& l) {
    __half2 hv = __floats2half2_rn(a, b);
    float2 hf = __half22float2(hv);
    __half2 lv = __floats2half2_rn(a - hf.x, b - hf.y);
    h = *(uint32_t*)&hv;
    l = *(uint32_t*)&lv;
}

// ---------------------------------------------------------------------------
// fp32 -> fp16 hi/lo split (same layout)
// ---------------------------------------------------------------------------
__global__ __launch_bounds__(256) void cvt_hilo(
    const float* __restrict__ in, __half* __restrict__ hi,
    __half* __restrict__ lo, int n)
{
    int i = (blockIdx.x * 256 + threadIdx.x) * 4;
    if (i >= n) return;
    float4 v = *(const float4*)(in + i);
    float f[4] = {v.x, v.y, v.z, v.w};
    __align__(8) __half hb[4];
    __align__(8) __half lb[4];
#pragma unroll
    for (int j = 0; j < 4; j++) {
        hb[j] = __float2half_rn(f[j]);
        lb[j] = __float2half_rn(f[j] - __half2float(hb[j]));
    }
    *(uint2*)(hi + i) = *(uint2*)hb;
    *(uint2*)(lo + i) = *(uint2*)lb;
}

// ---------------------------------------------------------------------------
// W [K,N] fp32 row-major -> W^T hi/lo fp16 [N,K]
// ---------------------------------------------------------------------------
__global__ __launch_bounds__(256) void cvt_w_t(
    const float* __restrict__ W, __half* __restrict__ Thi,
    __half* __restrict__ Tlo, int K, int N)
{
    __shared__ float tile[32][33];
    const int n0 = blockIdx.x * 32, k0 = blockIdx.y * 32;
    const int tx = threadIdx.x & 31, ty = threadIdx.x >> 5;   // 32 x 8
#pragma unroll
    for (int r = 0; r < 4; r++)
        tile[ty + 8 * r][tx] = W[(size_t)(k0 + ty + 8 * r) * N + n0 + tx];
    __syncthreads();
#pragma unroll
    for (int r = 0; r < 4; r++) {
        int n = n0 + ty + 8 * r;
        float v = tile[tx][ty + 8 * r];
        __half h = __float2half_rn(v);
        __half l = __float2half_rn(v - __half2float(h));
        Thi[(size_t)n * K + k0 + tx] = h;
        Tlo[(size_t)n * K + k0 + tx] = l;
    }
}

// ---------------------------------------------------------------------------
// mma.sync fp16 split GEMM: C[M,N] = A[M,K] @ B^T  (A [M,K] hi/lo, B [N,K])
// NP=3: Ahi*Bhi + Alo*Bhi + Ahi*Blo  (needs Blo)
// NP=2: Ahi*Bhi + Alo*Bhi            (B quantized to fp16; no Blo tile at all)
// CTA: 128x256 tile, BK=64, 256 threads (8 warps, 2Mx4N, warp tile 64x64),
// cp.async double-buffered, ONE __syncthreads per k-chunk.
// MODE 0: fp32 out; MODE 1: hi/lo fp16 out.
// ---------------------------------------------------------------------------
#define BK_G   64
#define LDT    72                        // 64 + 8 pad (fp16 elems) -> 144B rows
#define MAT_A  (128 * LDT * 2)           // 18432 B (A hi or lo, 128 rows)
#define MAT_Bb (256 * LDT * 2)           // 36864 B (B hi or lo, 256 rows)
#define SMEM_G3 (2 * (2 * MAT_A + 2 * MAT_Bb))   // 221184 B
#define SMEM_G2 (2 * (2 * MAT_A + 1 * MAT_Bb))   // 147456 B

template<int MODE, int NP>
__global__ __launch_bounds__(256, 1)
void gemm_mma_f16(const __half* __restrict__ Ahi,
                  const __half* __restrict__ Alo,
                  const __half* __restrict__ Bhi,
                  const __half* __restrict__ Blo,
                  float* __restrict__ Cf,
                  __half* __restrict__ Chi,
                  __half* __restrict__ Clo,
                  int N, int K)
{
    constexpr int BUF_B = 2 * MAT_A + (NP == 3 ? 2 : 1) * MAT_Bb;

    extern __shared__ __align__(128) char smem[];
    const int t    = threadIdx.x;
    const int lane = t & 31;
    const int wid  = t >> 5;
    const int bn   = blockIdx.x * 256;
    const int bm   = blockIdx.y * 128;
    const int wm   = (wid & 1) * 64;      // 2 warps in M
    const int wn   = (wid >> 1) * 64;     // 4 warps in N

    float acc[4][8][4];
#pragma unroll
    for (int i = 0; i < 4; i++)
#pragma unroll
        for (int j = 0; j < 8; j++)
#pragma unroll
            for (int r = 0; r < 4; r++) acc[i][j][r] = 0.f;

    const int nk = K / BK_G;   // 16

    auto load_tile = [&](int c, int buf) {
        char* bp = smem + buf * BUF_B;
        const int kc = c * BK_G;
        // A hi/lo: 128 rows x 8 chunks of 16B
#pragma unroll
        for (int i = 0; i < 4; i++) {
            int idx = t + 256 * i;
            int row = idx >> 3;            // 0..127
            int c16 = idx & 7;
            uint32_t so = (uint32_t)(row * LDT + c16 * 8) * 2;
            size_t ga = (size_t)(bm + row) * K + kc + c16 * 8;
            cp16(bp + so,         Ahi + ga);
            cp16(bp + MAT_A + so, Alo + ga);
        }
        // B: 256 rows x 8 chunks of 16B (hi always, lo only for NP=3)
#pragma unroll
        for (int i = 0; i < 8; i++) {
            int idx = t + 256 * i;
            int row = idx >> 3;            // 0..255
            int c16 = idx & 7;
            uint32_t so = (uint32_t)(row * LDT + c16 * 8) * 2;
            size_t gb = (size_t)(bn + row) * K + kc + c16 * 8;
            cp16(bp + 2 * MAT_A + so, Bhi + gb);
            if (NP == 3)
                cp16(bp + 2 * MAT_A + MAT_Bb + so, Blo + gb);
        }
    };

    load_tile(0, 0);
    asm volatile("cp.async.commit_group;" ::: "memory");

    for (int c = 0; c < nk; c++) {
        asm volatile("cp.async.wait_group 0;" ::: "memory");
        __syncthreads();                   // loads(c) visible; compute(c-1) drained
        if (c + 1 < nk) {
            load_tile(c + 1, (c + 1) & 1);
            asm volatile("cp.async.commit_group;" ::: "memory");
        }

        const char* bp = smem + (c & 1) * BUF_B;
        const __half* sAhi = (const __half*)(bp);
        const __half* sAlo = (const __half*)(bp + MAT_A);
        const __half* sBhi = (const __half*)(bp + 2 * MAT_A);
        const __half* sBlo = (const __half*)(bp + 2 * MAT_A + MAT_Bb);

#pragma unroll
        for (int ks = 0; ks < BK_G; ks += 16) {
            uint32_t ah[4][4], al[4][4], bh[4][4], bl[4][4];
            const int arow = lane & 15;
            const int acol = ks + (lane >> 4) * 8;
#pragma unroll
            for (int mf = 0; mf < 4; mf++) {
                uint32_t off = (uint32_t)((wm + mf * 16 + arow) * LDT + acol);
                ldx4(ah[mf], smem_u32(sAhi + off));
                ldx4(al[mf], smem_u32(sAlo + off));
            }
            const int g    = lane >> 3;
            const int brow = ((g >> 1) << 3) + (lane & 7);
            const int bcol = ks + (g & 1) * 8;
#pragma unroll
            for (int nf2 = 0; nf2 < 4; nf2++) {
                uint32_t off = (uint32_t)((wn + nf2 * 16 + brow) * LDT + bcol);
                ldx4(bh[nf2], smem_u32(sBhi + off));
                if (NP == 3) ldx4(bl[nf2], smem_u32(sBlo + off));
            }
#pragma unroll
            for (int p = 0; p < NP; p++)
#pragma unroll
                for (int mf = 0; mf < 4; mf++)
#pragma unroll
                    for (int nf2 = 0; nf2 < 4; nf2++)
#pragma unroll
                        for (int j = 0; j < 2; j++) {
                            const uint32_t* av = (p == 1) ? al[mf] : ah[mf];
                            const uint32_t* bv = (p == 2) ? &bl[nf2][j * 2]
                                                          : &bh[nf2][j * 2];
                            mma_f16(acc[mf][nf2 * 2 + j], av, bv);
                        }
        }
    }

#pragma unroll
    for (int mf = 0; mf < 4; mf++)
#pragma unroll
        for (int nf = 0; nf < 8; nf++) {
            int row = bm + wm + mf * 16 + (lane >> 2);
            int col = bn + wn + nf * 8 + (lane & 3) * 2;
            if (MODE == 0) {
                *(float2*)&Cf[(size_t)row * N + col] =
                    make_float2(acc[mf][nf][0], acc[mf][nf][1]);
                *(float2*)&Cf[(size_t)(row + 8) * N + col] =
                    make_float2(acc[mf][nf][2], acc[mf][nf][3]);
            } else {
                uint32_t h, l;
                pack_hilo(acc[mf][nf][0], acc[mf][nf][1], h, l);
                *(uint32_t*)&Chi[(size_t)row * N + col] = h;
                *(uint32_t*)&Clo[(size_t)row * N + col] = l;
                pack_hilo(acc[mf][nf][2], acc[mf][nf][3], h, l);
                *(uint32_t*)&Chi[(size_t)(row + 8) * N + col] = h;
                *(uint32_t*)&Clo[(size_t)(row + 8) * N + col] = l;
            }
        }
}

// ---------------------------------------------------------------------------
// Tensor-core flash attention, fp16 2-product, K/V DOUBLE-BUFFERED:
//   S = (Qhi+Qlo) K_hi^T ; O = (Phi+Plo) V_hi
// CTA 128 threads (4 warps), 64-q tile, 64-k blocks, 2048 CTAs.
// Per block: wait(KV jb) -> sync -> issue KV(jb+1) -> compute(jb).
// smem: Qh Ql + 2 stages of (Kh Vh) = 55296 B.
// ---------------------------------------------------------------------------
#define LDA_A 72
#define TILE_E (64 * LDA_A)                 // elems per smem matrix
#define ATTN_SMEM (6 * TILE_E * 2)          // Qh Ql + 2x(Kh Vh) = 55296 B

__global__ __launch_bounds__(128) void attn_mma(
    const __half* __restrict__ Shi, const __half* __restrict__ Slo,
    __half* __restrict__ Yhi, __half* __restrict__ Ylo)
{
    extern __shared__ __align__(16) char smraw[];
    __half* Qh  = (__half*)smraw;
    __half* Ql  = Qh + TILE_E;
    __half* KV0 = Ql + TILE_E;          // stage s at KV0 + s*2*TILE_E: Kh, Vh

    const int it = blockIdx.x;          // q-tile (0..31)
    const int h  = blockIdx.y;
    const int b  = blockIdx.z;
    const int t  = threadIdx.x;
    const int lane = t & 31;
    const int wid  = t >> 5;
    const int wq   = wid * 16;          // warp's q-row offset in tile

    const int q0   = it * 64;
    const size_t tok0 = (size_t)b * L_;
    const int qcol = h * D_;
    const int kcol = C_ + h * D_;
    const int vcol = 2 * C_ + h * D_;

    auto load_kv = [&](int jb, int st) {
        __half* Kh = KV0 + st * 2 * TILE_E;
        __half* Vh = Kh + TILE_E;
        const int k0 = jb * 64;
#pragma unroll
        for (int i = 0; i < 4; i++) {
            int idx = t + 128 * i;
            int row = idx >> 3;
            int ch  = (idx & 7) * 8;
            size_t gk = (tok0 + k0 + row) * (3 * C_) + kcol + ch;
            size_t gv = (tok0 + k0 + row) * (3 * C_) + vcol + ch;
            uint32_t so = row * LDA_A + ch;
            cp16(Kh + so, Shi + gk);
            cp16(Vh + so, Shi + gv);
        }
    };

    // ---- prologue: Q tile (group0), KV block 0 (group1) ----
#pragma unroll
    for (int i = 0; i < 4; i++) {
        int idx = t + 128 * i;
        int row = idx >> 3;
        int ch  = (idx & 7) * 8;
        size_t g = (tok0 + q0 + row) * (3 * C_) + qcol + ch;
        cp16(Qh + row * LDA_A + ch, Shi + g);
        cp16(Ql + row * LDA_A + ch, Slo + g);
    }
    asm volatile("cp.async.commit_group;" ::: "memory");
    load_kv(0, 0);
    asm volatile("cp.async.commit_group;" ::: "memory");
    asm volatile("cp.async.wait_group 1;" ::: "memory");   // Q ready, KV0 in flight
    __syncthreads();

    // ---- Q fragments (A-frags, m16k16 x 4 kgroups, hi+lo) ----
    uint32_t qh[4][4], ql[4][4];
    {
        const int arow = lane & 15;
        const int acol = (lane >> 4) * 8;
#pragma unroll
        for (int kg = 0; kg < 4; kg++) {
            uint32_t off = (uint32_t)((wq + arow) * LDA_A + kg * 16 + acol);
            ldx4(qh[kg], smem_u32(Qh + off));
            ldx4(ql[kg], smem_u32(Ql + off));
        }
    }

    const int r0 = lane >> 2;           // row pair within m16
    float m[2] = {-1e30f, -1e30f};
    float lsum[2] = {0.f, 0.f};
    float O[8][4];
#pragma unroll
    for (int f = 0; f < 8; f++)
#pragma unroll
        for (int e = 0; e < 4; e++) O[f][e] = 0.f;

    for (int jb = 0; jb <= it; jb++) {
        const int k0 = jb * 64;
        asm volatile("cp.async.wait_group 0;" ::: "memory");  // KV(jb) arrived
        __syncthreads();      // all warps: see KV(jb); compute(jb-1) drained
        if (jb + 1 <= it) {   // overwrites stage (jb+1)&1, freed by the sync
            load_kv(jb + 1, (jb + 1) & 1);
            asm volatile("cp.async.commit_group;" ::: "memory");
        }

        const __half* Kh = KV0 + (jb & 1) * 2 * TILE_E;
        const __half* Vh = Kh + TILE_E;

        // ---- S = (Qhi+Qlo) Kh^T (scores frags: 8 x n8) ----
        float s[8][4];
#pragma unroll
        for (int f = 0; f < 8; f++)
#pragma unroll
            for (int e = 0; e < 4; e++) s[f][e] = 0.f;

        {
            const int g    = lane >> 3;
            const int brow = ((g >> 1) << 3) + (lane & 7);
            const int bcol = (g & 1) * 8;
#pragma unroll
            for (int kg = 0; kg < 4; kg++) {
#pragma unroll
                for (int nf2 = 0; nf2 < 4; nf2++) {
                    uint32_t kh[4];
                    uint32_t off = (uint32_t)((nf2 * 16 + brow) * LDA_A + kg * 16 + bcol);
                    ldx4(kh, smem_u32(Kh + off));
#pragma unroll
                    for (int j = 0; j < 2; j++) {
                        float* d = s[nf2 * 2 + j];
                        mma_f16(d, qh[kg], &kh[j * 2]);
                        mma_f16(d, ql[kg], &kh[j * 2]);
                    }
                }
            }
        }

        // ---- scale + causal mask ----
        const bool diag = (jb == it);
#pragma unroll
        for (int f = 0; f < 8; f++) {
#pragma unroll
            for (int e = 0; e < 4; e++) {
                int qi = q0 + wq + r0 + (e >> 1) * 8;
                int ki = k0 + f * 8 + (lane & 3) * 2 + (e & 1);
                float v = s[f][e] * 0.125f;
                s[f][e] = (diag && ki > qi) ? -1e30f : v;
            }
        }

        // ---- online softmax (rows r0, r0+8) ----
#pragma unroll
        for (int r = 0; r < 2; r++) {
            float vmax = -1e30f;
#pragma unroll
            for (int f = 0; f < 8; f++)
                vmax = fmaxf(vmax, fmaxf(s[f][2 * r], s[f][2 * r + 1]));
            vmax = fmaxf(vmax, __shfl_xor_sync(0xffffffffu, vmax, 1));
            vmax = fmaxf(vmax, __shfl_xor_sync(0xffffffffu, vmax, 2));
            float nm = fmaxf(m[r], vmax);
            float alpha = __expf(m[r] - nm);
            m[r] = nm;
            float rs = 0.f;
#pragma unroll
            for (int f = 0; f < 8; f++) {
                float p0 = __expf(s[f][2 * r] - nm);
                float p1 = __expf(s[f][2 * r + 1] - nm);
                s[f][2 * r] = p0; s[f][2 * r + 1] = p1;
                rs += p0 + p1;
            }
            rs += __shfl_xor_sync(0xffffffffu, rs, 1);
            rs += __shfl_xor_sync(0xffffffffu, rs, 2);
            lsum[r] = lsum[r] * alpha + rs;
#pragma unroll
            for (int f = 0; f < 8; f++) {
                O[f][2 * r] *= alpha;
                O[f][2 * r + 1] *= alpha;
            }
        }

        // ---- O += (Phi+Plo) Vh (V via ldmatrix.trans) ----
        {
            const int g = lane >> 3;
            const int vrow = (g & 1) * 8 + (lane & 7);
            const int vcolb = (g >> 1) * 8;
#pragma unroll
            for (int kg = 0; kg < 4; kg++) {
                uint32_t pa_h[4], pa_l[4];
                pack_hilo(s[2 * kg][0],     s[2 * kg][1],     pa_h[0], pa_l[0]);
                pack_hilo(s[2 * kg][2],     s[2 * kg][3],     pa_h[1], pa_l[1]);
                pack_hilo(s[2 * kg + 1][0], s[2 * kg + 1][1], pa_h[2], pa_l[2]);
                pack_hilo(s[2 * kg + 1][2], s[2 * kg + 1][3], pa_h[3], pa_l[3]);
#pragma unroll
                for (int nf2 = 0; nf2 < 4; nf2++) {
                    uint32_t vh[4];
                    uint32_t off = (uint32_t)((kg * 16 + vrow) * LDA_A + nf2 * 16 + vcolb);
                    ldx4t(vh, smem_u32(Vh + off));
#pragma unroll
                    for (int j = 0; j < 2; j++) {
                        float* d = O[nf2 * 2 + j];
                        mma_f16(d, pa_h, &vh[j * 2]);
                        mma_f16(d, pa_l, &vh[j * 2]);
                    }
                }
            }
        }
    }

    // ---- normalize + write hi/lo fp16 output [token, C] ----
    const float inv0 = 1.0f / lsum[0];
    const float inv1 = 1.0f / lsum[1];
#pragma unroll
    for (int f = 0; f < 8; f++) {
        int col = h * D_ + f * 8 + (lane & 3) * 2;
        size_t row0 = (tok0 + q0 + wq + r0) * C_ + col;
        size_t row1 = (tok0 + q0 + wq + r0 + 8) * C_ + col;
        uint32_t hh, ll;
        pack_hilo(O[f][0] * inv0, O[f][1] * inv0, hh, ll);
        *(uint32_t*)&Yhi[row0] = hh;
        *(uint32_t*)&Ylo[row0] = ll;
        pack_hilo(O[f][2] * inv1, O[f][3] * inv1, hh, ll);
        *(uint32_t*)&Yhi[row1] = hh;
        *(uint32_t*)&Ylo[row1] = ll;
    }
}

// ---------------------------------------------------------------------------

extern "C" void kernel_launch(void* const* d_in, const int* in_sizes, int n_in,
                              void* d_out, int out_size)
{
    const float* x      = (const float*)d_in[0];   // [4,2048,1024]
    const float* w_attn = (const float*)d_in[1];   // [1024,3072]
    const float* w_proj = (const float*)d_in[2];   // [1024,1024]
    float* out = (float*)d_out;                    // [4,2048,1024]

    __half *ahi, *alo, *bhi, *blo, *shi, *slo;
    cudaGetSymbolAddress((void**)&ahi, g_Ahi);
    cudaGetSymbolAddress((void**)&alo, g_Alo);
    cudaGetSymbolAddress((void**)&bhi, g_Bhi);
    cudaGetSymbolAddress((void**)&blo, g_Blo);
    cudaGetSymbolAddress((void**)&shi, g_Shi);
    cudaGetSymbolAddress((void**)&slo, g_Slo);

    cudaFuncSetAttribute(gemm_mma_f16<1, 2>,
                         cudaFuncAttributeMaxDynamicSharedMemorySize, SMEM_G2);
    cudaFuncSetAttribute(gemm_mma_f16<0, 2>,
                         cudaFuncAttributeMaxDynamicSharedMemorySize, SMEM_G2);
    cudaFuncSetAttribute(attn_mma,
                         cudaFuncAttributeMaxDynamicSharedMemorySize, ATTN_SMEM);

    const int nA = MTOK * C_;

    // 1) split x -> fp16 hi/lo ; transpose+split w_attn -> [3C, C]
    cvt_hilo<<<nA / 4 / 256, 256>>>(x, ahi, alo, nA);
    cvt_w_t<<<dim3(3 * C_ / 32, C_ / 32), 256>>>(w_attn, bhi, blo, C_, 3 * C_);

    // 2) QKV GEMM (fp16, 2 products: (Ahi+Alo)·Bhi) -> hi/lo fp16 QKV
    gemm_mma_f16<1, 2><<<dim3(3 * C_ / 256, MTOK / 128), 256, SMEM_G2>>>(
        ahi, alo, bhi, blo, nullptr, shi, slo, 3 * C_, C_);

    // 3) tensor-core causal flash attention (2-product, KV double-buffered)
    attn_mma<<<dim3(L_ / 64, H_, B_), 128, ATTN_SMEM>>>(shi, slo, ahi, alo);

    // 4) transpose+split w_proj
    cvt_w_t<<<dim3(C_ / 32, C_ / 32), 256>>>(w_proj, bhi, blo, C_, C_);

    // 5) proj GEMM (2-product, no Blo tile) -> fp32 out
    gemm_mma_f16<0, 2><<<dim3(C_ / 256, MTOK / 128), 256, SMEM_G2>>>(
        ahi, alo, bhi, blo, out, nullptr, nullptr, C_, C_);
}

// round 17
// speedup vs baseline: 1.7142x; 1.0677x over previous
#include <cuda_runtime.h>
#include <cuda_fp16.h>
#include <cstdint>

#define B_ 4
#define L_ 2048
#define C_ 1024
#define H_ 16
#define D_ 64
#define MTOK (B_ * L_)   // 8192 token rows

// ---------------------------------------------------------------------------
// Scratch (allocation-free rule: __device__ globals)
// ---------------------------------------------------------------------------
__device__ __half g_Ahi[(size_t)MTOK * C_];     // activation hi  [M,K]
__device__ __half g_Alo[(size_t)MTOK * C_];     // activation lo  [M,K]
__device__ __half g_Bhi[(size_t)3 * C_ * C_];   // weight^T hi    [N,K]
__device__ __half g_Blo[(size_t)3 * C_ * C_];   // weight^T lo    [N,K]
__device__ __half g_Shi[(size_t)MTOK * 3 * C_]; // QKV hi [8192,3072]
__device__ __half g_Slo[(size_t)MTOK * 3 * C_]; // QKV lo

// ---------------------------------------------------------------------------
// helpers
// ---------------------------------------------------------------------------
__device__ __forceinline__ uint32_t smem_u32(const void* p) {
    return (uint32_t)__cvta_generic_to_shared(p);
}
__device__ __forceinline__ void cp16(void* s, const void* g) {
    uint32_t sa = smem_u32(s);
    asm volatile("cp.async.cg.shared.global [%0], [%1], 16;" :: "r"(sa), "l"(g) : "memory");
}
__device__ __forceinline__ void ldx4(uint32_t* r, uint32_t addr) {
    asm volatile("ldmatrix.sync.aligned.m8n8.x4.shared.b16 {%0,%1,%2,%3}, [%4];"
                 : "=r"(r[0]), "=r"(r[1]), "=r"(r[2]), "=r"(r[3]) : "r"(addr));
}
__device__ __forceinline__ void ldx4t(uint32_t* r, uint32_t addr) {
    asm volatile("ldmatrix.sync.aligned.m8n8.x4.trans.shared.b16 {%0,%1,%2,%3}, [%4];"
                 : "=r"(r[0]), "=r"(r[1]), "=r"(r[2]), "=r"(r[3]) : "r"(addr));
}
__device__ __forceinline__ void mma_f16(float* d, const uint32_t* a, const uint32_t* b) {
    asm volatile(
        "mma.sync.aligned.m16n8k16.row.col.f32.f16.f16.f32 "
        "{%0,%1,%2,%3}, {%4,%5,%6,%7}, {%8,%9}, {%0,%1,%2,%3};"
        : "+f"(d[0]), "+f"(d[1]), "+f"(d[2]), "+f"(d[3])
        : "r"(a[0]), "r"(a[1]), "r"(a[2]), "r"(a[3]), "r"(b[0]), "r"(b[1]));
}
// pack two floats into fp16x2 hi + fp16x2 lo (residual)
__device__ __forceinline__ void pack_hilo(float a, float b, uint32_t& h, uint32_t& l) {
    __half2 hv = __floats2half2_rn(a, b);
    float2 hf = __half22float2(hv);
    __half2 lv = __floats2half2_rn(a - hf.x, b - hf.y);
    h = *(uint32_t*)&hv;
    l = *(uint32_t*)&lv;
}
__device__ __forceinline__ uint32_t pack_h(float a, float b) {
    __half2 hv = __floats2half2_rn(a, b);
    return *(uint32_t*)&hv;
}

// ---------------------------------------------------------------------------
// fp32 -> fp16 hi/lo split (same layout)
// ---------------------------------------------------------------------------
__global__ __launch_bounds__(256) void cvt_hilo(
    const float* __restrict__ in, __half* __restrict__ hi,
    __half* __restrict__ lo, int n)
{
    int i = (blockIdx.x * 256 + threadIdx.x) * 4;
    if (i >= n) return;
    float4 v = *(const float4*)(in + i);
    float f[4] = {v.x, v.y, v.z, v.w};
    __align__(8) __half hb[4];
    __align__(8) __half lb[4];
#pragma unroll
    for (int j = 0; j < 4; j++) {
        hb[j] = __float2half_rn(f[j]);
        lb[j] = __float2half_rn(f[j] - __half2float(hb[j]));
    }
    *(uint2*)(hi + i) = *(uint2*)hb;
    *(uint2*)(lo + i) = *(uint2*)lb;
}

// ---------------------------------------------------------------------------
// W [K,N] fp32 row-major -> W^T hi/lo fp16 [N,K]
// ---------------------------------------------------------------------------
__global__ __launch_bounds__(256) void cvt_w_t(
    const float* __restrict__ W, __half* __restrict__ Thi,
    __half* __restrict__ Tlo, int K, int N)
{
    __shared__ float tile[32][33];
    const int n0 = blockIdx.x * 32, k0 = blockIdx.y * 32;
    const int tx = threadIdx.x & 31, ty = threadIdx.x >> 5;   // 32 x 8
#pragma unroll
    for (int r = 0; r < 4; r++)
        tile[ty + 8 * r][tx] = W[(size_t)(k0 + ty + 8 * r) * N + n0 + tx];
    __syncthreads();
#pragma unroll
    for (int r = 0; r < 4; r++) {
        int n = n0 + ty + 8 * r;
        float v = tile[tx][ty + 8 * r];
        __half h = __float2half_rn(v);
        __half l = __float2half_rn(v - __half2float(h));
        Thi[(size_t)n * K + k0 + tx] = h;
        Tlo[(size_t)n * K + k0 + tx] = l;
    }
}

// ---------------------------------------------------------------------------
// mma.sync fp16 split GEMM: C[M,N] = A[M,K] @ B^T  (A [M,K] hi/lo, B [N,K])
// NP=2: Ahi*Bhi + Alo*Bhi  (B quantized to fp16; no Blo tile)
// CTA: 128x256 tile, BK=64, 256 threads (8 warps, 2Mx4N, warp tile 64x64),
// cp.async double-buffered, ONE __syncthreads per k-chunk.
// MODE 0: fp32 out; MODE 1: hi/lo fp16 out.
// ---------------------------------------------------------------------------
#define BK_G   64
#define LDT    72                        // 64 + 8 pad (fp16 elems) -> 144B rows
#define MAT_A  (128 * LDT * 2)           // 18432 B (A hi or lo, 128 rows)
#define MAT_Bb (256 * LDT * 2)           // 36864 B (B hi or lo, 256 rows)
#define SMEM_G2 (2 * (2 * MAT_A + 1 * MAT_Bb))   // 147456 B

template<int MODE, int NP>
__global__ __launch_bounds__(256, 1)
void gemm_mma_f16(const __half* __restrict__ Ahi,
                  const __half* __restrict__ Alo,
                  const __half* __restrict__ Bhi,
                  const __half* __restrict__ Blo,
                  float* __restrict__ Cf,
                  __half* __restrict__ Chi,
                  __half* __restrict__ Clo,
                  int N, int K)
{
    constexpr int BUF_B = 2 * MAT_A + (NP == 3 ? 2 : 1) * MAT_Bb;

    extern __shared__ __align__(128) char smem[];
    const int t    = threadIdx.x;
    const int lane = t & 31;
    const int wid  = t >> 5;
    const int bn   = blockIdx.x * 256;
    const int bm   = blockIdx.y * 128;
    const int wm   = (wid & 1) * 64;      // 2 warps in M
    const int wn   = (wid >> 1) * 64;     // 4 warps in N

    float acc[4][8][4];
#pragma unroll
    for (int i = 0; i < 4; i++)
#pragma unroll
        for (int j = 0; j < 8; j++)
#pragma unroll
            for (int r = 0; r < 4; r++) acc[i][j][r] = 0.f;

    const int nk = K / BK_G;   // 16

    auto load_tile = [&](int c, int buf) {
        char* bp = smem + buf * BUF_B;
        const int kc = c * BK_G;
#pragma unroll
        for (int i = 0; i < 4; i++) {
            int idx = t + 256 * i;
            int row = idx >> 3;            // 0..127
            int c16 = idx & 7;
            uint32_t so = (uint32_t)(row * LDT + c16 * 8) * 2;
            size_t ga = (size_t)(bm + row) * K + kc + c16 * 8;
            cp16(bp + so,         Ahi + ga);
            cp16(bp + MAT_A + so, Alo + ga);
        }
#pragma unroll
        for (int i = 0; i < 8; i++) {
            int idx = t + 256 * i;
            int row = idx >> 3;            // 0..255
            int c16 = idx & 7;
            uint32_t so = (uint32_t)(row * LDT + c16 * 8) * 2;
            size_t gb = (size_t)(bn + row) * K + kc + c16 * 8;
            cp16(bp + 2 * MAT_A + so, Bhi + gb);
            if (NP == 3)
                cp16(bp + 2 * MAT_A + MAT_Bb + so, Blo + gb);
        }
    };

    load_tile(0, 0);
    asm volatile("cp.async.commit_group;" ::: "memory");

    for (int c = 0; c < nk; c++) {
        asm volatile("cp.async.wait_group 0;" ::: "memory");
        __syncthreads();                   // loads(c) visible; compute(c-1) drained
        if (c + 1 < nk) {
            load_tile(c + 1, (c + 1) & 1);
            asm volatile("cp.async.commit_group;" ::: "memory");
        }

        const char* bp = smem + (c & 1) * BUF_B;
        const __half* sAhi = (const __half*)(bp);
        const __half* sAlo = (const __half*)(bp + MAT_A);
        const __half* sBhi = (const __half*)(bp + 2 * MAT_A);
        const __half* sBlo = (const __half*)(bp + 2 * MAT_A + MAT_Bb);

#pragma unroll
        for (int ks = 0; ks < BK_G; ks += 16) {
            uint32_t ah[4][4], al[4][4], bh[4][4], bl[4][4];
            const int arow = lane & 15;
            const int acol = ks + (lane >> 4) * 8;
#pragma unroll
            for (int mf = 0; mf < 4; mf++) {
                uint32_t off = (uint32_t)((wm + mf * 16 + arow) * LDT + acol);
                ldx4(ah[mf], smem_u32(sAhi + off));
                ldx4(al[mf], smem_u32(sAlo + off));
            }
            const int g    = lane >> 3;
            const int brow = ((g >> 1) << 3) + (lane & 7);
            const int bcol = ks + (g & 1) * 8;
#pragma unroll
            for (int nf2 = 0; nf2 < 4; nf2++) {
                uint32_t off = (uint32_t)((wn + nf2 * 16 + brow) * LDT + bcol);
                ldx4(bh[nf2], smem_u32(sBhi + off));
                if (NP == 3) ldx4(bl[nf2], smem_u32(sBlo + off));
            }
#pragma unroll
            for (int p = 0; p < NP; p++)
#pragma unroll
                for (int mf = 0; mf < 4; mf++)
#pragma unroll
                    for (int nf2 = 0; nf2 < 4; nf2++)
#pragma unroll
                        for (int j = 0; j < 2; j++) {
                            const uint32_t* av = (p == 1) ? al[mf] : ah[mf];
                            const uint32_t* bv = (p == 2) ? &bl[nf2][j * 2]
                                                          : &bh[nf2][j * 2];
                            mma_f16(acc[mf][nf2 * 2 + j], av, bv);
                        }
        }
    }

#pragma unroll
    for (int mf = 0; mf < 4; mf++)
#pragma unroll
        for (int nf = 0; nf < 8; nf++) {
            int row = bm + wm + mf * 16 + (lane >> 2);
            int col = bn + wn + nf * 8 + (lane & 3) * 2;
            if (MODE == 0) {
                *(float2*)&Cf[(size_t)row * N + col] =
                    make_float2(acc[mf][nf][0], acc[mf][nf][1]);
                *(float2*)&Cf[(size_t)(row + 8) * N + col] =
                    make_float2(acc[mf][nf][2], acc[mf][nf][3]);
            } else {
                uint32_t h, l;
                pack_hilo(acc[mf][nf][0], acc[mf][nf][1], h, l);
                *(uint32_t*)&Chi[(size_t)row * N + col] = h;
                *(uint32_t*)&Clo[(size_t)row * N + col] = l;
                pack_hilo(acc[mf][nf][2], acc[mf][nf][3], h, l);
                *(uint32_t*)&Chi[(size_t)(row + 8) * N + col] = h;
                *(uint32_t*)&Clo[(size_t)(row + 8) * N + col] = l;
            }
        }
}

// ---------------------------------------------------------------------------
// Tensor-core flash attention, fp16:
//   S = (Qhi+Qlo) K_hi^T   (2 products)
//   O = P_hi V_hi          (1 product; P in [0,1], fp16 quant err ~2e-4)
// CTA 128 threads (4 warps), 64-q tile, 64-k blocks, 2048 CTAs.
// smem: 4 tile slots (36.9 KB). Q occupies slots 0,1 only until fragment
// extraction, then odd KV stages overlay them. Even stages use slots 2,3.
// __launch_bounds__(128,4): cap regs at 128 so 4 CTAs/SM are resident.
// ---------------------------------------------------------------------------
#define LDA_A 72
#define TILE_E (64 * LDA_A)                 // elems per smem tile slot
#define ATTN_SMEM (4 * TILE_E * 2)          // 36864 B

__global__ __launch_bounds__(128, 4) void attn_mma(
    const __half* __restrict__ Shi, const __half* __restrict__ Slo,
    __half* __restrict__ Yhi, __half* __restrict__ Ylo)
{
    extern __shared__ __align__(16) char smraw[];
    __half* slot0 = (__half*)smraw;          // Qh, later odd-stage Kh
    __half* slot2 = slot0 + 2 * TILE_E;      // even-stage Kh

    const int it = blockIdx.x;          // q-tile (0..31)
    const int h  = blockIdx.y;
    const int b  = blockIdx.z;
    const int t  = threadIdx.x;
    const int lane = t & 31;
    const int wid  = t >> 5;
    const int wq   = wid * 16;          // warp's q-row offset in tile

    const int q0   = it * 64;
    const size_t tok0 = (size_t)b * L_;
    const int qcol = h * D_;
    const int kcol = C_ + h * D_;
    const int vcol = 2 * C_ + h * D_;

    auto load_kv = [&](int jb) {
        __half* Kh = (jb & 1) ? slot0 : slot2;   // odd stages overlay Q slots
        __half* Vh = Kh + TILE_E;
        const int k0 = jb * 64;
#pragma unroll
        for (int i = 0; i < 4; i++) {
            int idx = t + 128 * i;
            int row = idx >> 3;
            int ch  = (idx & 7) * 8;
            size_t gk = (tok0 + k0 + row) * (3 * C_) + kcol + ch;
            size_t gv = (tok0 + k0 + row) * (3 * C_) + vcol + ch;
            uint32_t so = row * LDA_A + ch;
            cp16(Kh + so, Shi + gk);
            cp16(Vh + so, Shi + gv);
        }
    };

    // ---- prologue: Q tile -> slots 0,1 (group0); KV block 0 -> slots 2,3 ----
#pragma unroll
    for (int i = 0; i < 4; i++) {
        int idx = t + 128 * i;
        int row = idx >> 3;
        int ch  = (idx & 7) * 8;
        size_t g = (tok0 + q0 + row) * (3 * C_) + qcol + ch;
        cp16(slot0 + row * LDA_A + ch, Shi + g);
        cp16(slot0 + TILE_E + row * LDA_A + ch, Slo + g);
    }
    asm volatile("cp.async.commit_group;" ::: "memory");
    load_kv(0);
    asm volatile("cp.async.commit_group;" ::: "memory");
    asm volatile("cp.async.wait_group 1;" ::: "memory");   // Q ready, KV0 in flight
    __syncthreads();

    // ---- Q fragments (A-frags, m16k16 x 4 kgroups, hi+lo) ----
    uint32_t qh[4][4], ql[4][4];
    {
        const int arow = lane & 15;
        const int acol = (lane >> 4) * 8;
#pragma unroll
        for (int kg = 0; kg < 4; kg++) {
            uint32_t off = (uint32_t)((wq + arow) * LDA_A + kg * 16 + acol);
            ldx4(qh[kg], smem_u32(slot0 + off));
            ldx4(ql[kg], smem_u32(slot0 + TILE_E + off));
        }
    }
    __syncthreads();   // all warps hold Q frags; slots 0,1 are now reusable

    const int r0 = lane >> 2;           // row pair within m16
    float m[2] = {-1e30f, -1e30f};
    float lsum[2] = {0.f, 0.f};
    float O[8][4];
#pragma unroll
    for (int f = 0; f < 8; f++)
#pragma unroll
        for (int e = 0; e < 4; e++) O[f][e] = 0.f;

    for (int jb = 0; jb <= it; jb++) {
        const int k0 = jb * 64;
        asm volatile("cp.async.wait_group 0;" ::: "memory");  // KV(jb) arrived
        __syncthreads();      // all warps: see KV(jb); compute(jb-1) drained
        if (jb + 1 <= it) {   // stage (jb+1)&1 is free (Q dead / compute drained)
            load_kv(jb + 1);
            asm volatile("cp.async.commit_group;" ::: "memory");
        }

        const __half* Kh = (jb & 1) ? slot0 : slot2;
        const __half* Vh = Kh + TILE_E;

        // ---- S = (Qhi+Qlo) Kh^T (scores frags: 8 x n8) ----
        float s[8][4];
#pragma unroll
        for (int f = 0; f < 8; f++)
#pragma unroll
            for (int e = 0; e < 4; e++) s[f][e] = 0.f;

        {
            const int g    = lane >> 3;
            const int brow = ((g >> 1) << 3) + (lane & 7);
            const int bcol = (g & 1) * 8;
#pragma unroll
            for (int kg = 0; kg < 4; kg++) {
#pragma unroll
                for (int nf2 = 0; nf2 < 4; nf2++) {
                    uint32_t kh[4];
                    uint32_t off = (uint32_t)((nf2 * 16 + brow) * LDA_A + kg * 16 + bcol);
                    ldx4(kh, smem_u32(Kh + off));
#pragma unroll
                    for (int j = 0; j < 2; j++) {
                        float* d = s[nf2 * 2 + j];
                        mma_f16(d, qh[kg], &kh[j * 2]);
                        mma_f16(d, ql[kg], &kh[j * 2]);
                    }
                }
            }
        }

        // ---- scale + causal mask ----
        const bool diag = (jb == it);
#pragma unroll
        for (int f = 0; f < 8; f++) {
#pragma unroll
            for (int e = 0; e < 4; e++) {
                int qi = q0 + wq + r0 + (e >> 1) * 8;
                int ki = k0 + f * 8 + (lane & 3) * 2 + (e & 1);
                float v = s[f][e] * 0.125f;
                s[f][e] = (diag && ki > qi) ? -1e30f : v;
            }
        }

        // ---- online softmax (rows r0, r0+8) ----
#pragma unroll
        for (int r = 0; r < 2; r++) {
            float vmax = -1e30f;
#pragma unroll
            for (int f = 0; f < 8; f++)
                vmax = fmaxf(vmax, fmaxf(s[f][2 * r], s[f][2 * r + 1]));
            vmax = fmaxf(vmax, __shfl_xor_sync(0xffffffffu, vmax, 1));
            vmax = fmaxf(vmax, __shfl_xor_sync(0xffffffffu, vmax, 2));
            float nm = fmaxf(m[r], vmax);
            float alpha = __expf(m[r] - nm);
            m[r] = nm;
            float rs = 0.f;
#pragma unroll
            for (int f = 0; f < 8; f++) {
                float p0 = __expf(s[f][2 * r] - nm);
                float p1 = __expf(s[f][2 * r + 1] - nm);
                s[f][2 * r] = p0; s[f][2 * r + 1] = p1;
                rs += p0 + p1;
            }
            rs += __shfl_xor_sync(0xffffffffu, rs, 1);
            rs += __shfl_xor_sync(0xffffffffu, rs, 2);
            lsum[r] = lsum[r] * alpha + rs;
#pragma unroll
            for (int f = 0; f < 8; f++) {
                O[f][2 * r] *= alpha;
                O[f][2 * r + 1] *= alpha;
            }
        }

        // ---- O += P_hi Vh (single product; V via ldmatrix.trans) ----
        {
            const int g = lane >> 3;
            const int vrow = (g & 1) * 8 + (lane & 7);
            const int vcolb = (g >> 1) * 8;
#pragma unroll
            for (int kg = 0; kg < 4; kg++) {
                uint32_t pa[4];
                pa[0] = pack_h(s[2 * kg][0],     s[2 * kg][1]);
                pa[1] = pack_h(s[2 * kg][2],     s[2 * kg][3]);
                pa[2] = pack_h(s[2 * kg + 1][0], s[2 * kg + 1][1]);
                pa[3] = pack_h(s[2 * kg + 1][2], s[2 * kg + 1][3]);
#pragma unroll
                for (int nf2 = 0; nf2 < 4; nf2++) {
                    uint32_t vh[4];
                    uint32_t off = (uint32_t)((kg * 16 + vrow) * LDA_A + nf2 * 16 + vcolb);
                    ldx4t(vh, smem_u32(Vh + off));
#pragma unroll
                    for (int j = 0; j < 2; j++)
                        mma_f16(O[nf2 * 2 + j], pa, &vh[j * 2]);
                }
            }
        }
    }

    // ---- normalize + write hi/lo fp16 output [token, C] ----
    const float inv0 = 1.0f / lsum[0];
    const float inv1 = 1.0f / lsum[1];
#pragma unroll
    for (int f = 0; f < 8; f++) {
        int col = h * D_ + f * 8 + (lane & 3) * 2;
        size_t row0 = (tok0 + q0 + wq + r0) * C_ + col;
        size_t row1 = (tok0 + q0 + wq + r0 + 8) * C_ + col;
        uint32_t hh, ll;
        pack_hilo(O[f][0] * inv0, O[f][1] * inv0, hh, ll);
        *(uint32_t*)&Yhi[row0] = hh;
        *(uint32_t*)&Ylo[row0] = ll;
        pack_hilo(O[f][2] * inv1, O[f][3] * inv1, hh, ll);
        *(uint32_t*)&Yhi[row1] = hh;
        *(uint32_t*)&Ylo[row1] = ll;
    }
}

// ---------------------------------------------------------------------------

extern "C" void kernel_launch(void* const* d_in, const int* in_sizes, int n_in,
                              void* d_out, int out_size)
{
    const float* x      = (const float*)d_in[0];   // [4,2048,1024]
    const float* w_attn = (const float*)d_in[1];   // [1024,3072]
    const float* w_proj = (const float*)d_in[2];   // [1024,1024]
    float* out = (float*)d_out;                    // [4,2048,1024]

    __half *ahi, *alo, *bhi, *blo, *shi, *slo;
    cudaGetSymbolAddress((void**)&ahi, g_Ahi);
    cudaGetSymbolAddress((void**)&alo, g_Alo);
    cudaGetSymbolAddress((void**)&bhi, g_Bhi);
    cudaGetSymbolAddress((void**)&blo, g_Blo);
    cudaGetSymbolAddress((void**)&shi, g_Shi);
    cudaGetSymbolAddress((void**)&slo, g_Slo);

    cudaFuncSetAttribute(gemm_mma_f16<1, 2>,
                         cudaFuncAttributeMaxDynamicSharedMemorySize, SMEM_G2);
    cudaFuncSetAttribute(gemm_mma_f16<0, 2>,
                         cudaFuncAttributeMaxDynamicSharedMemorySize, SMEM_G2);
    cudaFuncSetAttribute(attn_mma,
                         cudaFuncAttributeMaxDynamicSharedMemorySize, ATTN_SMEM);

    const int nA = MTOK * C_;

    // 1) split x -> fp16 hi/lo ; transpose+split w_attn -> [3C, C]
    cvt_hilo<<<nA / 4 / 256, 256>>>(x, ahi, alo, nA);
    cvt_w_t<<<dim3(3 * C_ / 32, C_ / 32), 256>>>(w_attn, bhi, blo, C_, 3 * C_);

    // 2) QKV GEMM (fp16, 2 products: (Ahi+Alo)·Bhi) -> hi/lo fp16 QKV
    gemm_mma_f16<1, 2><<<dim3(3 * C_ / 256, MTOK / 128), 256, SMEM_G2>>>(
        ahi, alo, bhi, blo, nullptr, shi, slo, 3 * C_, C_);

    // 3) tensor-core causal flash attention -> hi/lo into proj bufs
    attn_mma<<<dim3(L_ / 64, H_, B_), 128, ATTN_SMEM>>>(shi, slo, ahi, alo);

    // 4) transpose+split w_proj
    cvt_w_t<<<dim3(C_ / 32, C_ / 32), 256>>>(w_proj, bhi, blo, C_, C_);

    // 5) proj GEMM (2-product, no Blo tile) -> fp32 out
    gemm_mma_f16<0, 2><<<dim3(C_ / 256, MTOK / 128), 256, SMEM_G2>>>(
        ahi, alo, bhi, blo, out, nullptr, nullptr, C_, C_);
}